// round 11
// baseline (speedup 1.0000x reference)
#include <cuda_runtime.h>
#include <cuda_fp16.h>

// SwinV2 shifted-window attention, B=16, H=W=64, C=256, heads=8, hd=32.
// Round 11: QKV + attention FUSED into one kernel (one window per CTA).
// q/k/v never touch gmem: K hi/lo and V live in smem planes, Q and P stay
// in registers (GEMM C-frag == MMA A-frag identity). Saves ~336 MB of
// intermediate traffic. Proj unchanged from round 10.

#define NWIN   1024
#define NTOK   64
#define CDIM   256
#define NHEAD  8
#define HD     32

// -------- scratch (device globals; no allocation) --------
__device__ unsigned short g_ao [NWIN * NTOK * CDIM];   // attn out fp16
__device__ unsigned short g_xh [16 * 64 * 64 * CDIM];  // x fp16
__device__ unsigned short g_wh [4 * CDIM * CDIM];      // W^T fp16 [n][k]
__device__ float          g_bias16[NHEAD * 225];
__device__ float          g_scale[NHEAD];

// -------- helpers --------
__device__ __forceinline__ unsigned pkh(float lo, float hi) {
    unsigned r;
    asm("cvt.rn.f16x2.f32 %0, %1, %2;" : "=r"(r) : "f"(hi), "f"(lo));
    return r;
}
__device__ __forceinline__ void mma16(float* c, const unsigned* a, const unsigned* b) {
    asm volatile("mma.sync.aligned.m16n8k16.row.col.f32.f16.f16.f32 "
                 "{%0,%1,%2,%3},{%4,%5,%6,%7},{%8,%9},{%0,%1,%2,%3};"
                 : "+f"(c[0]), "+f"(c[1]), "+f"(c[2]), "+f"(c[3])
                 : "r"(a[0]), "r"(a[1]), "r"(a[2]), "r"(a[3]),
                   "r"(b[0]), "r"(b[1]));
}
__device__ __forceinline__ void ldsm4(unsigned* r, unsigned addr) {
    asm volatile("ldmatrix.sync.aligned.m8n8.x4.shared.b16 {%0,%1,%2,%3}, [%4];"
                 : "=r"(r[0]), "=r"(r[1]), "=r"(r[2]), "=r"(r[3]) : "r"(addr));
}
__device__ __forceinline__ void ldsm4t(unsigned* r, unsigned addr) {
    asm volatile("ldmatrix.sync.aligned.m8n8.x4.trans.shared.b16 {%0,%1,%2,%3}, [%4];"
                 : "=r"(r[0]), "=r"(r[1]), "=r"(r[2]), "=r"(r[3]) : "r"(addr));
}
__device__ __forceinline__ void cp16(unsigned dst, const void* src) {
    asm volatile("cp.async.cg.shared.global [%0], [%1], 16;" :: "r"(dst), "l"(src));
}
__device__ __forceinline__ void cp_commit() {
    asm volatile("cp.async.commit_group;");
}
template<int N> __device__ __forceinline__ void cp_wait() {
    asm volatile("cp.async.wait_group %0;" :: "n"(N));
}

// -------- fused kernel smem geometry --------
// staging: A 64x144B + B 256x144B per stage, 2 stages
// planes : per head 64 rows x 80B (20 u32, conflict-free ldmatrix)
#define FA_BYTES  (64 * 144)                 // 9216
#define FSTG      (FA_BYTES + 256 * 144)     // 46080
#define FS_ROWB   0                          // 64 u32
#define FS_SCL    256                        // 8 f32
#define FS_BIAS   512                        // 3*256 f32 = 3072
#define FS_BTAB   3584                       // 8*226 f32 = 7232
#define FS_KH     10880                      // 8*64*80 = 40960
#define FS_KL     51840                      // 40960
#define FS_V      92800                      // 40960
#define FS_STG    133760                     // 2*46080 = 92160
#define F_SMEM    225920

// -------- proj kernel smem geometry (round 10) --------
#define A_BYTES   (128 * 144)
#define STG_BYTES (A_BYTES + 256 * 144)
#define SM_BIAS   1024
#define SM_BUF    4096
#define G_SMEM    (SM_BUF + 3 * STG_BYTES)

// ============================================================
// Kernel 0: continuous-position-bias MLP
// ============================================================
__global__ void swin_bias_kernel(const float* __restrict__ ls,
                                 const float* __restrict__ w1,
                                 const float* __restrict__ b1,
                                 const float* __restrict__ w2)
{
    __shared__ float part[16][8];
    const int t   = blockIdx.x;
    const int i   = t / 15;
    const int j   = t % 15;
    const int tid = threadIdx.x;
    const int warp = tid >> 5;
    const int lane = tid & 31;

    float rh = (float)(i - 7) * (8.0f / 7.0f);
    float rw = (float)(j - 7) * (8.0f / 7.0f);
    rh = copysignf(log2f(fabsf(rh) + 1.0f) * (1.0f / 3.0f), rh);
    rw = copysignf(log2f(fabsf(rw) + 1.0f) * (1.0f / 3.0f), rw);

    float hv = fmaxf(0.0f, rh * w1[tid] + rw * w1[512 + tid] + b1[tid]);

    float p[8];
#pragma unroll
    for (int h = 0; h < 8; ++h) p[h] = hv * w2[tid * 8 + h];
#pragma unroll
    for (int off = 16; off; off >>= 1)
#pragma unroll
        for (int h = 0; h < 8; ++h) p[h] += __shfl_xor_sync(0xffffffffu, p[h], off);
    if (lane == 0)
#pragma unroll
        for (int h = 0; h < 8; ++h) part[warp][h] = p[h];
    __syncthreads();

    if (tid < 8) {
        float s = 0.0f;
#pragma unroll
        for (int g = 0; g < 16; ++g) s += part[g][tid];
        g_bias16[tid * 225 + t] = 16.0f / (1.0f + expf(-s));
    }
    if (blockIdx.x == 0 && tid < 8)
        g_scale[tid] = expf(fminf(ls[tid], 4.6051701860f));
}

// ============================================================
// Kernel 0b: x -> fp16; W -> transposed fp16 [n][k]
// ============================================================
__global__ void swin_cvt_kernel(const float* __restrict__ x,
                                const float* __restrict__ Wq,
                                const float* __restrict__ Wk,
                                const float* __restrict__ Wv,
                                const float* __restrict__ Wo)
{
    const int blk = blockIdx.x;
    const int tid = threadIdx.x;
    if (blk < 16384) {
        int i4 = blk * 256 + tid;
        float4 v = ((const float4*)x)[i4];
        ((uint2*)g_xh)[i4] = make_uint2(pkh(v.x, v.y), pkh(v.z, v.w));
    } else {
        int r = blk - 16384;
        int m = r >> 6;
        const float* W = (m == 0) ? Wq : (m == 1) ? Wk : (m == 2) ? Wv : Wo;
        int idx = (r & 63) * 256 + tid;
        int n  = idx >> 6;
        int k4 = (idx & 63) * 4;
        float a0 = W[(k4 + 0) * 256 + n];
        float a1 = W[(k4 + 1) * 256 + n];
        float a2 = W[(k4 + 2) * 256 + n];
        float a3 = W[(k4 + 3) * 256 + n];
        ((uint2*)(g_wh + m * 65536))[idx] = make_uint2(pkh(a0, a1), pkh(a2, a3));
    }
}

// ============================================================
// Kernel 1: FUSED QKV projection + attention. grid 1024 (1 window), 512 thr.
// GEMM order: m=0:K, m=1:V, m=2:Q. K hi/lo + V go to smem planes; Q stays
// in registers; attention runs in the Q epilogue; only g_ao is written.
// ============================================================
__global__ void __launch_bounds__(512)
swin_qkva_kernel(const float* __restrict__ bq,
                 const float* __restrict__ bk,
                 const float* __restrict__ bv)
{
    extern __shared__ char smem[];
    const unsigned sb = (unsigned)__cvta_generic_to_shared(smem);
    unsigned* rowb_s = (unsigned*)(smem + FS_ROWB);
    float*    scl_s  = (float*)(smem + FS_SCL);
    float*    bias_s = (float*)(smem + FS_BIAS);
    float*    btab_s = (float*)(smem + FS_BTAB);
    unsigned* khs    = (unsigned*)(smem + FS_KH);
    unsigned* kls    = (unsigned*)(smem + FS_KL);
    unsigned* vns    = (unsigned*)(smem + FS_V);

    const int w    = blockIdx.x;
    const int b    = w >> 6;
    const int wy   = (w >> 3) & 7;
    const int wx   = w & 7;
    const int tid  = threadIdx.x;
    const int warp = tid >> 5;
    const int lane = tid & 31;
    const int g    = lane >> 2;
    const int t    = lane & 3;
    const int mw   = warp >> 2;            // M 16-slice (rows mw*16..+16)
    const int nq   = warp & 3;             // N 64-slice (heads 2nq, 2nq+1)

    const unsigned alm = lane & 15;
    const unsigned alk = (lane >> 4) << 4;
    const unsigned blm = (lane & 7) + ((lane >> 4) << 3);
    const unsigned blk = ((lane >> 3) & 1) << 4;

    if (tid < 64) {
        int sy = ((wy << 3) + (tid >> 3) + 4) & 63;
        int sx = ((wx << 3) + (tid & 7) + 4) & 63;
        rowb_s[tid] = ((((b << 6) | sy) << 6) | sx) << 8;
    }
    if (tid < 256) {
        bias_s[tid]       = bk[tid];       // m=0 : K
        bias_s[256 + tid] = bv[tid];       // m=1 : V
        bias_s[512 + tid] = bq[tid];       // m=2 : Q
    }
    for (int i = tid; i < 1800; i += 512) {
        int h = i / 225, j = i % 225;
        btab_s[h * 226 + j] = g_bias16[i];
    }
    if (tid < 8) scl_s[tid] = g_scale[tid];
    __syncthreads();

    const int arow = tid >> 3;             // 0..63
    const int ajj  = tid & 7;
    const unsigned rbA = rowb_s[arow];

#define STAGE(wm_, c_, st_) do {                                               \
        unsigned _a = sb + FS_STG + (st_) * FSTG;                              \
        cp16(_a + arow * 144 + ajj * 16, g_xh + rbA + (c_) * 64 + ajj * 8);    \
        unsigned _bB = _a + FA_BYTES;                                          \
        _Pragma("unroll")                                                      \
        for (int _i = 0; _i < 4; ++_i) {                                       \
            int _n = arow + _i * 64;                                           \
            cp16(_bB + _n * 144 + ajj * 16,                                    \
                 (wm_) + _n * 256 + (c_) * 64 + ajj * 8);                      \
        }                                                                      \
        cp_commit();                                                           \
    } while (0)

    const unsigned short* Wm[3] = { g_wh + 65536, g_wh + 2 * 65536, g_wh };

    STAGE(Wm[0], 0, 0);
    STAGE(Wm[0], 1, 1);

    float acc[8][4];
    const bool mhb = (wy == 7), mwb = (wx == 7);
    const int r0 = mw * 16 + g;
    const int r1 = r0 + 8;

#pragma unroll 1
    for (int ts = 0; ts < 12; ++ts) {
        const int m  = ts >> 2;
        const int c  = ts & 3;
        const int st = ts & 1;

        if (c == 0) {
#pragma unroll
            for (int nt = 0; nt < 8; ++nt)
#pragma unroll
                for (int q = 0; q < 4; ++q) acc[nt][q] = 0.0f;
        }

        if (ts == 11) cp_wait<0>(); else cp_wait<1>();
        __syncthreads();

        const unsigned sbX = sb + FS_STG + st * FSTG;
        const unsigned sbB = sbX + FA_BYTES;
#pragma unroll
        for (int ks = 0; ks < 4; ++ks) {
            unsigned a4[4];
            ldsm4(a4, sbX + (mw * 16 + alm) * 144 + ks * 32 + alk);
#pragma unroll
            for (int ntp = 0; ntp < 4; ++ntp) {
                unsigned b4[4];
                ldsm4(b4, sbB + (nq * 64 + ntp * 16 + blm) * 144 + ks * 32 + blk);
                mma16(acc[2 * ntp],     a4, b4);
                mma16(acc[2 * ntp + 1], a4, b4 + 2);
            }
        }
        __syncthreads();

        if (ts + 2 < 12) {
            int t2 = ts + 2;
            STAGE(Wm[t2 >> 2], t2 & 3, st);
        }

        if (c == 3) {
            // ---- epilogue for matrix m ----
            float2 bb[8];
#pragma unroll
            for (int nt = 0; nt < 8; ++nt)
                bb[nt] = *(float2*)(bias_s + m * 256 + nq * 64 + nt * 8 + 2 * t);
#pragma unroll
            for (int nt = 0; nt < 8; ++nt) {
                acc[nt][0] += bb[nt].x;  acc[nt][1] += bb[nt].y;
                acc[nt][2] += bb[nt].x;  acc[nt][3] += bb[nt].y;
            }

            if (m != 1) {
                // cosine normalization (K and Q)
#pragma unroll
                for (int rh = 0; rh < 2; ++rh)
#pragma unroll
                    for (int hh = 0; hh < 2; ++hh) {
                        float s = 0.0f;
#pragma unroll
                        for (int k2 = 0; k2 < 4; ++k2) {
                            int nt = hh * 4 + k2;
                            s += acc[nt][rh * 2]     * acc[nt][rh * 2]
                               + acc[nt][rh * 2 + 1] * acc[nt][rh * 2 + 1];
                        }
                        s += __shfl_xor_sync(0xffffffffu, s, 1);
                        s += __shfl_xor_sync(0xffffffffu, s, 2);
                        float inv = 1.0f / fmaxf(sqrtf(s), 1e-12f);
#pragma unroll
                        for (int k2 = 0; k2 < 4; ++k2) {
                            int nt = hh * 4 + k2;
                            acc[nt][rh * 2]     *= inv;
                            acc[nt][rh * 2 + 1] *= inv;
                        }
                    }
            }

            if (m == 0) {
                // K -> smem planes (hi/lo)
#pragma unroll
                for (int hh = 0; hh < 2; ++hh) {
                    int head = nq * 2 + hh;
                    unsigned* khp = khs + head * 1280;
                    unsigned* klp = kls + head * 1280;
#pragma unroll
                    for (int nt2 = 0; nt2 < 4; ++nt2) {
                        int nt = hh * 4 + nt2;
                        int wi = nt2 * 4 + t;
                        unsigned h0 = pkh(acc[nt][0], acc[nt][1]);
                        float2 f0 = __half22float2(*(__half2*)&h0);
                        unsigned l0 = pkh(acc[nt][0] - f0.x, acc[nt][1] - f0.y);
                        unsigned h1 = pkh(acc[nt][2], acc[nt][3]);
                        float2 f1 = __half22float2(*(__half2*)&h1);
                        unsigned l1 = pkh(acc[nt][2] - f1.x, acc[nt][3] - f1.y);
                        khp[r0 * 20 + wi] = h0;  klp[r0 * 20 + wi] = l0;
                        khp[r1 * 20 + wi] = h1;  klp[r1 * 20 + wi] = l1;
                    }
                }
            } else if (m == 1) {
                // V -> smem plane (natural fp16)
#pragma unroll
                for (int hh = 0; hh < 2; ++hh) {
                    int head = nq * 2 + hh;
                    unsigned* vp = vns + head * 1280;
#pragma unroll
                    for (int nt2 = 0; nt2 < 4; ++nt2) {
                        int nt = hh * 4 + nt2;
                        int wi = nt2 * 4 + t;
                        vp[r0 * 20 + wi] = pkh(acc[nt][0], acc[nt][1]);
                        vp[r1 * 20 + wi] = pkh(acc[nt][2], acc[nt][3]);
                    }
                }
            } else {
                // ================= ATTENTION (Q in registers) ===============
                const int ty0 = r0 >> 3, tx0 = r0 & 7;
                const int ty1 = r1 >> 3, tx1 = r1 & 7;
                unsigned* ao32 = (unsigned*)g_ao;

#pragma unroll 1
                for (int hh = 0; hh < 2; ++hh) {
                    const int head = nq * 2 + hh;
                    const float sc = scl_s[head];
                    const float* bsh = btab_s + head * 226;

                    // Q fragments straight from acc (hi/lo split in regs)
                    unsigned aqh[2][4], aql[2][4];
#pragma unroll
                    for (int ks = 0; ks < 2; ++ks) {
                        int n0 = hh * 4 + 2 * ks;
#pragma unroll
                        for (int p2 = 0; p2 < 2; ++p2) {      // n0, n0+1
#pragma unroll
                            for (int rh = 0; rh < 2; ++rh) {  // rows g, g+8
                                float vx = acc[n0 + p2][rh * 2];
                                float vy = acc[n0 + p2][rh * 2 + 1];
                                unsigned hw = pkh(vx, vy);
                                float2 hf = __half22float2(*(__half2*)&hw);
                                aqh[ks][p2 * 2 + rh] = hw;
                                aql[ks][p2 * 2 + rh] = pkh(vx - hf.x, vy - hf.y);
                            }
                        }
                    }

                    // QK^T (fp16 hi/lo 3-term)
                    const unsigned khb = sb + FS_KH + head * 5120;
                    const unsigned klb = sb + FS_KL + head * 5120;
                    float cc[8][4];
#pragma unroll
                    for (int nt = 0; nt < 8; ++nt)
#pragma unroll
                        for (int q = 0; q < 4; ++q) cc[nt][q] = 0.0f;

#pragma unroll
                    for (int ks = 0; ks < 2; ++ks) {
#pragma unroll
                        for (int ntp = 0; ntp < 4; ++ntp) {
                            unsigned off = (ntp * 16 + blm) * 80 + ks * 32 + blk;
                            unsigned rh4[4], rl4[4];
                            ldsm4(rh4, khb + off);
                            ldsm4(rl4, klb + off);
                            mma16(cc[2 * ntp],     aqh[ks], rh4);
                            mma16(cc[2 * ntp],     aql[ks], rh4);
                            mma16(cc[2 * ntp],     aqh[ks], rl4);
                            mma16(cc[2 * ntp + 1], aqh[ks], rh4 + 2);
                            mma16(cc[2 * ntp + 1], aql[ks], rh4 + 2);
                            mma16(cc[2 * ntp + 1], aqh[ks], rl4 + 2);
                        }
                    }

                    // bias + mask
#pragma unroll
                    for (int nt = 0; nt < 8; ++nt)
#pragma unroll
                        for (int q = 0; q < 4; ++q) {
                            int mm  = nt * 8 + 2 * t + (q & 1);
                            int my = mm >> 3, mxc = mm & 7;
                            int ty = (q < 2) ? ty0 : ty1;
                            int tx = (q < 2) ? tx0 : tx1;
                            float v = cc[nt][q] * sc + bsh[(ty - my + 7) * 15 + (tx - mxc + 7)];
                            if (mhb && ((ty < 4) != (my < 4)))  v -= 100.0f;
                            if (mwb && ((tx < 4) != (mxc < 4))) v -= 100.0f;
                            cc[nt][q] = v;
                        }

                    // softmax
                    float mx0 = -1e30f, mx1 = -1e30f;
#pragma unroll
                    for (int nt = 0; nt < 8; ++nt) {
                        mx0 = fmaxf(mx0, fmaxf(cc[nt][0], cc[nt][1]));
                        mx1 = fmaxf(mx1, fmaxf(cc[nt][2], cc[nt][3]));
                    }
                    mx0 = fmaxf(mx0, __shfl_xor_sync(0xffffffffu, mx0, 1));
                    mx0 = fmaxf(mx0, __shfl_xor_sync(0xffffffffu, mx0, 2));
                    mx1 = fmaxf(mx1, __shfl_xor_sync(0xffffffffu, mx1, 1));
                    mx1 = fmaxf(mx1, __shfl_xor_sync(0xffffffffu, mx1, 2));

                    float s0 = 0.0f, s1 = 0.0f;
#pragma unroll
                    for (int nt = 0; nt < 8; ++nt) {
                        cc[nt][0] = __expf(cc[nt][0] - mx0);
                        cc[nt][1] = __expf(cc[nt][1] - mx0);
                        cc[nt][2] = __expf(cc[nt][2] - mx1);
                        cc[nt][3] = __expf(cc[nt][3] - mx1);
                        s0 += cc[nt][0] + cc[nt][1];
                        s1 += cc[nt][2] + cc[nt][3];
                    }
                    s0 += __shfl_xor_sync(0xffffffffu, s0, 1);
                    s0 += __shfl_xor_sync(0xffffffffu, s0, 2);
                    s1 += __shfl_xor_sync(0xffffffffu, s1, 1);
                    s1 += __shfl_xor_sync(0xffffffffu, s1, 2);
                    const float inv0 = 1.0f / s0;
                    const float inv1 = 1.0f / s1;

                    // PV: P fragments straight from cc; V via ldmatrix.trans
                    const unsigned vbb = sb + FS_V + head * 5120;
                    float out[4][4];
#pragma unroll
                    for (int vt = 0; vt < 4; ++vt)
#pragma unroll
                        for (int q = 0; q < 4; ++q) out[vt][q] = 0.0f;

#pragma unroll
                    for (int kb = 0; kb < 4; ++kb) {
                        unsigned a4[4] = {
                            pkh(cc[2 * kb][0],     cc[2 * kb][1]),
                            pkh(cc[2 * kb][2],     cc[2 * kb][3]),
                            pkh(cc[2 * kb + 1][0], cc[2 * kb + 1][1]),
                            pkh(cc[2 * kb + 1][2], cc[2 * kb + 1][3]) };
#pragma unroll
                        for (int vtp = 0; vtp < 2; ++vtp) {
                            unsigned b4[4];
                            unsigned vaddr = vbb
                                + (kb * 16 + (lane & 7) + (((lane >> 3) & 1) << 3)) * 80
                                + vtp * 32 + ((lane >> 4) << 4);
                            ldsm4t(b4, vaddr);
                            mma16(out[2 * vtp],     a4, b4);
                            mma16(out[2 * vtp + 1], a4, b4 + 2);
                        }
                    }

                    // store fp16 to g_ao
                    const int d0i = (((w << 6) | r0) << 8) + head * 32;
                    const int d1i = (((w << 6) | r1) << 8) + head * 32;
#pragma unroll
                    for (int vt = 0; vt < 4; ++vt) {
                        ao32[(d0i + vt * 8 + 2 * t) >> 1] =
                            pkh(out[vt][0] * inv0, out[vt][1] * inv0);
                        ao32[(d1i + vt * 8 + 2 * t) >> 1] =
                            pkh(out[vt][2] * inv1, out[vt][3] * inv1);
                    }
                }
            }
        }
    }
#undef STAGE
}

// ============================================================
// Kernel 3: output projection fp16 + ldmatrix + inverse window/roll scatter.
// (unchanged from round 10)
// ============================================================
__global__ void __launch_bounds__(512)
swin_proj_kernel(const float* __restrict__ bo, float* __restrict__ out)
{
    extern __shared__ char smem[];
    const unsigned sb = (unsigned)__cvta_generic_to_shared(smem);
    float* bias_s = (float*)(smem + SM_BIAS);

    const int bw   = blockIdx.x;
    const int tid  = threadIdx.x;
    const int warp = tid >> 5;
    const int lane = tid & 31;
    const int g    = lane >> 2;
    const int t    = lane & 3;
    const int mw   = warp >> 2;
    const int nq   = warp & 3;

    const unsigned alm = lane & 15;
    const unsigned alk = (lane >> 4) << 4;
    const unsigned blm = (lane & 7) + ((lane >> 4) << 3);
    const unsigned blk = ((lane >> 3) & 1) << 4;

    if (tid < 256) bias_s[tid] = bo[tid];
    __syncthreads();

    const int srow = tid >> 3;
    const int sjj  = tid & 7;
    const unsigned asto0 = srow * 144 + sjj * 16;
    const unsigned asto1 = (srow + 64) * 144 + sjj * 16;
    const unsigned short* wh = g_wh + 3 * 65536;
    const int abase = bw * 128 * 256;

#define STAGE(c_, st_) do {                                                    \
        unsigned _a = sb + SM_BUF + (st_) * STG_BYTES;                         \
        cp16(_a + asto0, g_ao + abase + srow * 256 + (c_) * 64 + sjj * 8);     \
        cp16(_a + asto1, g_ao + abase + (srow + 64) * 256 + (c_) * 64 + sjj * 8); \
        unsigned _bB = _a + A_BYTES;                                           \
        _Pragma("unroll")                                                      \
        for (int _i = 0; _i < 4; ++_i) {                                       \
            int _n = srow + _i * 64;                                           \
            cp16(_bB + _n * 144 + sjj * 16, wh + _n * 256 + (c_) * 64 + sjj * 8); \
        }                                                                      \
        cp_commit();                                                           \
    } while (0)

    STAGE(0, 0);
    STAGE(1, 1);

    float acc[2][8][4];
#pragma unroll
    for (int mt = 0; mt < 2; ++mt)
#pragma unroll
        for (int nt = 0; nt < 8; ++nt)
#pragma unroll
            for (int q = 0; q < 4; ++q) acc[mt][nt][q] = 0.0f;

#pragma unroll 1
    for (int c = 0; c < 4; ++c) {
        const int st = c % 3;
        if (c == 3) cp_wait<0>(); else cp_wait<1>();
        __syncthreads();
        if (c + 2 < 4) STAGE(c + 2, (c + 2) % 3);

        const unsigned sbX = sb + SM_BUF + st * STG_BYTES;
        const unsigned sbB = sbX + A_BYTES;
#pragma unroll
        for (int ks = 0; ks < 4; ++ks) {
            unsigned a[2][4];
            ldsm4(a[0], sbX + (mw * 32 + alm) * 144 + ks * 32 + alk);
            ldsm4(a[1], sbX + (mw * 32 + 16 + alm) * 144 + ks * 32 + alk);
#pragma unroll
            for (int ntp = 0; ntp < 4; ++ntp) {
                unsigned b4[4];
                ldsm4(b4, sbB + (nq * 64 + ntp * 16 + blm) * 144 + ks * 32 + blk);
                mma16(acc[0][2 * ntp],     a[0], b4);
                mma16(acc[0][2 * ntp + 1], a[0], b4 + 2);
                mma16(acc[1][2 * ntp],     a[1], b4);
                mma16(acc[1][2 * ntp + 1], a[1], b4 + 2);
            }
        }
        __syncthreads();
    }
#undef STAGE

    float2 bb[8];
#pragma unroll
    for (int nt = 0; nt < 8; ++nt)
        bb[nt] = *(float2*)(bias_s + nq * 64 + nt * 8 + 2 * t);

#pragma unroll
    for (int mt = 0; mt < 2; ++mt)
#pragma unroll
        for (int rh = 0; rh < 2; ++rh)
#pragma unroll
            for (int nt = 0; nt < 8; ++nt) {
                int n   = mw * 32 + mt * 16 + rh * 8 + g;
                int wv  = bw * 2 + (n >> 6);
                int tok = n & 63;
                int b   = wv >> 6, wy = (wv >> 3) & 7, wx = wv & 7;
                int y   = ((wy << 3) + (tok >> 3) + 4) & 63;
                int xc  = ((wx << 3) + (tok & 7) + 4) & 63;
                int col = nq * 64 + nt * 8 + 2 * t;
                *(float2*)(out + (((b << 6) | y) << 14) + (xc << 8) + col) =
                    make_float2(acc[mt][nt][rh * 2] + bb[nt].x,
                                acc[mt][nt][rh * 2 + 1] + bb[nt].y);
            }
}

// ============================================================
extern "C" void kernel_launch(void* const* d_in, const int* in_sizes, int n_in,
                              void* d_out, int out_size)
{
    const float* x  = (const float*)d_in[0];
    const float* Wq = (const float*)d_in[1];
    const float* bq = (const float*)d_in[2];
    const float* Wk = (const float*)d_in[3];
    const float* bk = (const float*)d_in[4];
    const float* Wv = (const float*)d_in[5];
    const float* bv = (const float*)d_in[6];
    const float* Wo = (const float*)d_in[7];
    const float* bo = (const float*)d_in[8];
    const float* ls = (const float*)d_in[9];
    const float* w1 = (const float*)d_in[10];
    const float* b1 = (const float*)d_in[11];
    const float* w2 = (const float*)d_in[12];
    float* out = (float*)d_out;

    cudaFuncSetAttribute(swin_qkva_kernel,
                         cudaFuncAttributeMaxDynamicSharedMemorySize, F_SMEM);
    cudaFuncSetAttribute(swin_proj_kernel,
                         cudaFuncAttributeMaxDynamicSharedMemorySize, G_SMEM);

    swin_bias_kernel<<<225, 512>>>(ls, w1, b1, w2);
    swin_cvt_kernel<<<16640, 256>>>(x, Wq, Wk, Wv, Wo);
    swin_qkva_kernel<<<NWIN, 512, F_SMEM>>>(bq, bk, bv);
    swin_proj_kernel<<<512, 512, G_SMEM>>>(bo, out);
}

// round 12
// speedup vs baseline: 1.3599x; 1.3599x over previous
#include <cuda_runtime.h>
#include <cuda_fp16.h>

// SwinV2 shifted-window attention, B=16, H=W=64, C=256, heads=8, hd=32.
// Round 12: round-10 structure, but the QKV GEMM is split across the grid:
// blockIdx.y in {0,1,2} selects Q/K/V. Each CTA = one proj-shaped 4-chunk
// 3-stage pipelined GEMM with a per-matrix epilogue (Q->qh/ql, K->kh/kl,
// V->v16 planes). Attention and proj identical to round 10.

#define NWIN   1024
#define NTOK   64
#define CDIM   256
#define NHEAD  8
#define HD     32

// -------- scratch (device globals; no allocation) --------
__device__ unsigned       g_qh [NWIN * NHEAD * NTOK * 16];   // q hi f16x2 words
__device__ unsigned       g_ql [NWIN * NHEAD * NTOK * 16];   // q lo
__device__ unsigned       g_kh [NWIN * NHEAD * NTOK * 16];   // k hi
__device__ unsigned       g_kl [NWIN * NHEAD * NTOK * 16];   // k lo
__device__ unsigned       g_v16[NWIN * NHEAD * NTOK * 16];   // v f16x2 words
__device__ unsigned short g_ao [NWIN * NTOK * CDIM];         // attn out fp16
__device__ unsigned short g_xh [16 * 64 * 64 * CDIM];        // x fp16
__device__ unsigned short g_wh [4 * CDIM * CDIM];            // W^T fp16 [n][k]
__device__ float          g_bias16[NHEAD * 225];
__device__ float          g_scale[NHEAD];

// -------- helpers --------
__device__ __forceinline__ unsigned pkh(float lo, float hi) {
    unsigned r;
    asm("cvt.rn.f16x2.f32 %0, %1, %2;" : "=r"(r) : "f"(hi), "f"(lo));
    return r;
}
__device__ __forceinline__ void mma16(float* c, const unsigned* a, const unsigned* b) {
    asm volatile("mma.sync.aligned.m16n8k16.row.col.f32.f16.f16.f32 "
                 "{%0,%1,%2,%3},{%4,%5,%6,%7},{%8,%9},{%0,%1,%2,%3};"
                 : "+f"(c[0]), "+f"(c[1]), "+f"(c[2]), "+f"(c[3])
                 : "r"(a[0]), "r"(a[1]), "r"(a[2]), "r"(a[3]),
                   "r"(b[0]), "r"(b[1]));
}
__device__ __forceinline__ void ldsm4(unsigned* r, unsigned addr) {
    asm volatile("ldmatrix.sync.aligned.m8n8.x4.shared.b16 {%0,%1,%2,%3}, [%4];"
                 : "=r"(r[0]), "=r"(r[1]), "=r"(r[2]), "=r"(r[3]) : "r"(addr));
}
__device__ __forceinline__ void cp16(unsigned dst, const void* src) {
    asm volatile("cp.async.cg.shared.global [%0], [%1], 16;" :: "r"(dst), "l"(src));
}
__device__ __forceinline__ void cp_commit() {
    asm volatile("cp.async.commit_group;");
}
template<int N> __device__ __forceinline__ void cp_wait() {
    asm volatile("cp.async.wait_group %0;" :: "n"(N));
}

// -------- fp16 GEMM smem geometry --------
#define A_BYTES   (128 * 144)
#define STG_BYTES (A_BYTES + 256 * 144)
#define SM_ROWB   64
#define SM_BIAS   1024
#define SM_BUF    4096
#define G_SMEM    (SM_BUF + 3 * STG_BYTES)

// ============================================================
// Kernel 0: continuous-position-bias MLP
// ============================================================
__global__ void swin_bias_kernel(const float* __restrict__ ls,
                                 const float* __restrict__ w1,
                                 const float* __restrict__ b1,
                                 const float* __restrict__ w2)
{
    __shared__ float part[16][8];
    const int t   = blockIdx.x;
    const int i   = t / 15;
    const int j   = t % 15;
    const int tid = threadIdx.x;
    const int warp = tid >> 5;
    const int lane = tid & 31;

    float rh = (float)(i - 7) * (8.0f / 7.0f);
    float rw = (float)(j - 7) * (8.0f / 7.0f);
    rh = copysignf(log2f(fabsf(rh) + 1.0f) * (1.0f / 3.0f), rh);
    rw = copysignf(log2f(fabsf(rw) + 1.0f) * (1.0f / 3.0f), rw);

    float hv = fmaxf(0.0f, rh * w1[tid] + rw * w1[512 + tid] + b1[tid]);

    float p[8];
#pragma unroll
    for (int h = 0; h < 8; ++h) p[h] = hv * w2[tid * 8 + h];
#pragma unroll
    for (int off = 16; off; off >>= 1)
#pragma unroll
        for (int h = 0; h < 8; ++h) p[h] += __shfl_xor_sync(0xffffffffu, p[h], off);
    if (lane == 0)
#pragma unroll
        for (int h = 0; h < 8; ++h) part[warp][h] = p[h];
    __syncthreads();

    if (tid < 8) {
        float s = 0.0f;
#pragma unroll
        for (int g = 0; g < 16; ++g) s += part[g][tid];
        g_bias16[tid * 225 + t] = 16.0f / (1.0f + expf(-s));
    }
    if (blockIdx.x == 0 && tid < 8)
        g_scale[tid] = expf(fminf(ls[tid], 4.6051701860f));
}

// ============================================================
// Kernel 0b: x -> fp16; W -> transposed fp16 [n][k]
// ============================================================
__global__ void swin_cvt_kernel(const float* __restrict__ x,
                                const float* __restrict__ Wq,
                                const float* __restrict__ Wk,
                                const float* __restrict__ Wv,
                                const float* __restrict__ Wo)
{
    const int blk = blockIdx.x;
    const int tid = threadIdx.x;
    if (blk < 16384) {
        int i4 = blk * 256 + tid;
        float4 v = ((const float4*)x)[i4];
        ((uint2*)g_xh)[i4] = make_uint2(pkh(v.x, v.y), pkh(v.z, v.w));
    } else {
        int r = blk - 16384;
        int m = r >> 6;
        const float* W = (m == 0) ? Wq : (m == 1) ? Wk : (m == 2) ? Wv : Wo;
        int idx = (r & 63) * 256 + tid;
        int n  = idx >> 6;
        int k4 = (idx & 63) * 4;
        float a0 = W[(k4 + 0) * 256 + n];
        float a1 = W[(k4 + 1) * 256 + n];
        float a2 = W[(k4 + 2) * 256 + n];
        float a3 = W[(k4 + 3) * 256 + n];
        ((uint2*)(g_wh + m * 65536))[idx] = make_uint2(pkh(a0, a1), pkh(a2, a3));
    }
}

// ============================================================
// Kernel 1: one QKV matrix per CTA. grid (512, 3): y = 0:Q, 1:K, 2:V.
// M=128 (2 windows), N=256, K=256 in 4 chunks, 3-stage cp.async.
// ============================================================
__global__ void __launch_bounds__(512)
swin_qkv_kernel(const float* __restrict__ bq,
                const float* __restrict__ bk,
                const float* __restrict__ bv)
{
    extern __shared__ char smem[];
    const unsigned sb = (unsigned)__cvta_generic_to_shared(smem);
    unsigned* rowb_s = (unsigned*)(smem + SM_ROWB);
    float*    bias_s = (float*)(smem + SM_BIAS);

    const int bw   = blockIdx.x;
    const int m    = blockIdx.y;          // 0=Q, 1=K, 2=V
    const int tid  = threadIdx.x;
    const int warp = tid >> 5;
    const int lane = tid & 31;
    const int g    = lane >> 2;
    const int t    = lane & 3;
    const int mw   = warp >> 2;
    const int nq   = warp & 3;

    const unsigned alm = lane & 15;
    const unsigned alk = (lane >> 4) << 4;
    const unsigned blm = (lane & 7) + ((lane >> 4) << 3);
    const unsigned blk = ((lane >> 3) & 1) << 4;

    if (tid < 128) {
        int wv = bw * 2 + (tid >> 6);
        int b = wv >> 6, wy = (wv >> 3) & 7, wx = wv & 7;
        int tok = tid & 63;
        int sy = ((wy << 3) + (tok >> 3) + 4) & 63;
        int sx = ((wx << 3) + (tok & 7) + 4) & 63;
        rowb_s[tid] = ((((b << 6) | sy) << 6) | sx) << 8;
    }
    if (tid < 256) {
        const float* bp = (m == 0) ? bq : (m == 1) ? bk : bv;
        bias_s[tid] = bp[tid];
    }
    __syncthreads();

    const int srow = tid >> 3;
    const int sjj  = tid & 7;
    const unsigned rb0 = rowb_s[srow];
    const unsigned rb1 = rowb_s[srow + 64];
    const unsigned asto0 = srow * 144 + sjj * 16;
    const unsigned asto1 = (srow + 64) * 144 + sjj * 16;
    const unsigned short* wh = g_wh + m * 65536;   // cvt order: 0=Wq,1=Wk,2=Wv

#define STAGE(c_, st_) do {                                                    \
        unsigned _a = sb + SM_BUF + (st_) * STG_BYTES;                         \
        cp16(_a + asto0, g_xh + rb0 + (c_) * 64 + sjj * 8);                    \
        cp16(_a + asto1, g_xh + rb1 + (c_) * 64 + sjj * 8);                    \
        unsigned _bB = _a + A_BYTES;                                           \
        _Pragma("unroll")                                                      \
        for (int _i = 0; _i < 4; ++_i) {                                       \
            int _n = srow + _i * 64;                                           \
            cp16(_bB + _n * 144 + sjj * 16, wh + _n * 256 + (c_) * 64 + sjj * 8); \
        }                                                                      \
        cp_commit();                                                           \
    } while (0)

    STAGE(0, 0);
    STAGE(1, 1);

    float acc[2][8][4];
#pragma unroll
    for (int mt = 0; mt < 2; ++mt)
#pragma unroll
        for (int nt = 0; nt < 8; ++nt)
#pragma unroll
            for (int q = 0; q < 4; ++q) acc[mt][nt][q] = 0.0f;

#pragma unroll 1
    for (int c = 0; c < 4; ++c) {
        const int st = c % 3;
        if (c == 3) cp_wait<0>(); else cp_wait<1>();
        __syncthreads();
        if (c + 2 < 4) STAGE(c + 2, (c + 2) % 3);

        const unsigned sbX = sb + SM_BUF + st * STG_BYTES;
        const unsigned sbB = sbX + A_BYTES;
#pragma unroll
        for (int ks = 0; ks < 4; ++ks) {
            unsigned a[2][4];
            ldsm4(a[0], sbX + (mw * 32 + alm) * 144 + ks * 32 + alk);
            ldsm4(a[1], sbX + (mw * 32 + 16 + alm) * 144 + ks * 32 + alk);
#pragma unroll
            for (int ntp = 0; ntp < 4; ++ntp) {
                unsigned b4[4];
                ldsm4(b4, sbB + (nq * 64 + ntp * 16 + blm) * 144 + ks * 32 + blk);
                mma16(acc[0][2 * ntp],     a[0], b4);
                mma16(acc[0][2 * ntp + 1], a[0], b4 + 2);
                mma16(acc[1][2 * ntp],     a[1], b4);
                mma16(acc[1][2 * ntp + 1], a[1], b4 + 2);
            }
        }
        __syncthreads();
    }
#undef STAGE

    // ---- epilogue ----
    float2 bb[8];
#pragma unroll
    for (int nt = 0; nt < 8; ++nt)
        bb[nt] = *(float2*)(bias_s + nq * 64 + nt * 8 + 2 * t);
#pragma unroll
    for (int mt = 0; mt < 2; ++mt)
#pragma unroll
        for (int nt = 0; nt < 8; ++nt) {
            acc[mt][nt][0] += bb[nt].x;  acc[mt][nt][1] += bb[nt].y;
            acc[mt][nt][2] += bb[nt].x;  acc[mt][nt][3] += bb[nt].y;
        }

    if (m < 2) {   // cosine normalization for Q and K
#pragma unroll
        for (int mt = 0; mt < 2; ++mt)
#pragma unroll
            for (int rh = 0; rh < 2; ++rh)
#pragma unroll
                for (int hh = 0; hh < 2; ++hh) {
                    float s = 0.0f;
#pragma unroll
                    for (int k2 = 0; k2 < 4; ++k2) {
                        int nt = hh * 4 + k2;
                        s += acc[mt][nt][rh * 2]     * acc[mt][nt][rh * 2]
                           + acc[mt][nt][rh * 2 + 1] * acc[mt][nt][rh * 2 + 1];
                    }
                    s += __shfl_xor_sync(0xffffffffu, s, 1);
                    s += __shfl_xor_sync(0xffffffffu, s, 2);
                    float inv = 1.0f / fmaxf(sqrtf(s), 1e-12f);
#pragma unroll
                    for (int k2 = 0; k2 < 4; ++k2) {
                        int nt = hh * 4 + k2;
                        acc[mt][nt][rh * 2]     *= inv;
                        acc[mt][nt][rh * 2 + 1] *= inv;
                    }
                }
    }

#pragma unroll
    for (int mt = 0; mt < 2; ++mt)
#pragma unroll
        for (int rh = 0; rh < 2; ++rh)
#pragma unroll
            for (int nt = 0; nt < 8; ++nt) {
                int n    = mw * 32 + mt * 16 + rh * 8 + g;
                int win  = bw * 2 + (n >> 6);
                int tok  = n & 63;
                int col  = nq * 64 + nt * 8 + 2 * t;
                int head = col >> 5;
                int d    = col & 31;
                int idx  = (((win << 3) | head) << 10) + (tok << 4) + (d >> 1);
                float vx = acc[mt][nt][rh * 2];
                float vy = acc[mt][nt][rh * 2 + 1];
                if (m == 2) {
                    g_v16[idx] = pkh(vx, vy);
                } else {
                    unsigned hw = pkh(vx, vy);
                    float2 hf = __half22float2(*(__half2*)&hw);
                    unsigned lw = pkh(vx - hf.x, vy - hf.y);
                    if (m == 0) { g_qh[idx] = hw; g_ql[idx] = lw; }
                    else        { g_kh[idx] = hw; g_kl[idx] = lw; }
                }
            }
}

// ============================================================
// Kernel 2: fully-fp16 MMA attention + ldmatrix (round 10).
// grid (1024, 8), 128 threads.
// ============================================================
__global__ void __launch_bounds__(128)
swin_attn_kernel()
{
    __shared__ __align__(16) unsigned khs[64 * 20];
    __shared__ __align__(16) unsigned kls[64 * 20];
    __shared__ __align__(16) unsigned vts[32 * 36];
    __shared__ __align__(16) unsigned ps[4][16 * 36];
    __shared__ float bs[228];

    const int w    = blockIdx.x;
    const int h    = blockIdx.y;
    const int tid  = threadIdx.x;
    const int wt   = tid >> 5;
    const int lane = tid & 31;
    const int g    = lane >> 2;
    const int t    = lane & 3;
    const int pbase = ((w << 3) | h) << 10;

    const unsigned alm = lane & 15;
    const unsigned alk = (lane >> 4) << 4;
    const unsigned blm = (lane & 7) + ((lane >> 4) << 3);
    const unsigned blk = ((lane >> 3) & 1) << 4;

    const uint4* khp4 = (const uint4*)(g_kh + pbase);
    const uint4* klp4 = (const uint4*)(g_kl + pbase);
#pragma unroll
    for (int it = 0; it < 2; ++it) {
        int i4  = tid + it * 128;
        int row = i4 >> 2;
        int c4  = (i4 & 3) << 2;
        *(uint4*)(khs + row * 20 + c4) = khp4[i4];
        *(uint4*)(kls + row * 20 + c4) = klp4[i4];
    }

    {
        const int mp = tid & 31;
        const int dp = tid >> 5;
        const uint4* v4 = (const uint4*)(g_v16 + pbase);
        uint4 a = v4[(2 * mp) * 4 + dp];
        uint4 b = v4[(2 * mp + 1) * 4 + dp];
        int d0 = dp * 8;
        vts[(d0 + 0) * 36 + mp] = __byte_perm(a.x, b.x, 0x5410);
        vts[(d0 + 1) * 36 + mp] = __byte_perm(a.x, b.x, 0x7632);
        vts[(d0 + 2) * 36 + mp] = __byte_perm(a.y, b.y, 0x5410);
        vts[(d0 + 3) * 36 + mp] = __byte_perm(a.y, b.y, 0x7632);
        vts[(d0 + 4) * 36 + mp] = __byte_perm(a.z, b.z, 0x5410);
        vts[(d0 + 5) * 36 + mp] = __byte_perm(a.z, b.z, 0x7632);
        vts[(d0 + 6) * 36 + mp] = __byte_perm(a.w, b.w, 0x5410);
        vts[(d0 + 7) * 36 + mp] = __byte_perm(a.w, b.w, 0x7632);
    }
    for (int i = tid; i < 225; i += 128) bs[i] = g_bias16[h * 225 + i];
    __syncthreads();

    const float sc = g_scale[h];
    const int wy = (w >> 3) & 7, wx = w & 7;
    const bool mhb = (wy == 7), mwb = (wx == 7);
    const int r0 = wt * 16 + g;
    const int r1 = r0 + 8;

    const unsigned* qhp = g_qh + pbase;
    const unsigned* qlp = g_ql + pbase;
    unsigned aqh[2][4], aql[2][4];
#pragma unroll
    for (int ks = 0; ks < 2; ++ks) {
        int bidx = r0 * 16 + ks * 8 + t;
        aqh[ks][0] = qhp[bidx];        aqh[ks][1] = qhp[bidx + 128];
        aqh[ks][2] = qhp[bidx + 4];    aqh[ks][3] = qhp[bidx + 132];
        aql[ks][0] = qlp[bidx];        aql[ks][1] = qlp[bidx + 128];
        aql[ks][2] = qlp[bidx + 4];    aql[ks][3] = qlp[bidx + 132];
    }

    const unsigned khs_b = (unsigned)__cvta_generic_to_shared(khs);
    const unsigned kls_b = (unsigned)__cvta_generic_to_shared(kls);
    float cc[8][4];
#pragma unroll
    for (int nt = 0; nt < 8; ++nt)
#pragma unroll
        for (int q = 0; q < 4; ++q) cc[nt][q] = 0.0f;

#pragma unroll
    for (int ks = 0; ks < 2; ++ks) {
#pragma unroll
        for (int ntp = 0; ntp < 4; ++ntp) {
            unsigned off = (ntp * 16 + blm) * 80 + ks * 32 + blk;
            unsigned rh4[4], rl4[4];
            ldsm4(rh4, khs_b + off);
            ldsm4(rl4, kls_b + off);
            mma16(cc[2 * ntp],     aqh[ks], rh4);
            mma16(cc[2 * ntp],     aql[ks], rh4);
            mma16(cc[2 * ntp],     aqh[ks], rl4);
            mma16(cc[2 * ntp + 1], aqh[ks], rh4 + 2);
            mma16(cc[2 * ntp + 1], aql[ks], rh4 + 2);
            mma16(cc[2 * ntp + 1], aqh[ks], rl4 + 2);
        }
    }

    const int ty0 = r0 >> 3, tx0 = r0 & 7;
    const int ty1 = r1 >> 3, tx1 = r1 & 7;
#pragma unroll
    for (int nt = 0; nt < 8; ++nt)
#pragma unroll
        for (int q = 0; q < 4; ++q) {
            int m  = nt * 8 + 2 * t + (q & 1);
            int my = m >> 3, mxc = m & 7;
            int ty = (q < 2) ? ty0 : ty1;
            int tx = (q < 2) ? tx0 : tx1;
            float v = cc[nt][q] * sc + bs[(ty - my + 7) * 15 + (tx - mxc + 7)];
            if (mhb && ((ty < 4) != (my < 4)))  v -= 100.0f;
            if (mwb && ((tx < 4) != (mxc < 4))) v -= 100.0f;
            cc[nt][q] = v;
        }

    float mx0 = -1e30f, mx1 = -1e30f;
#pragma unroll
    for (int nt = 0; nt < 8; ++nt) {
        mx0 = fmaxf(mx0, fmaxf(cc[nt][0], cc[nt][1]));
        mx1 = fmaxf(mx1, fmaxf(cc[nt][2], cc[nt][3]));
    }
    mx0 = fmaxf(mx0, __shfl_xor_sync(0xffffffffu, mx0, 1));
    mx0 = fmaxf(mx0, __shfl_xor_sync(0xffffffffu, mx0, 2));
    mx1 = fmaxf(mx1, __shfl_xor_sync(0xffffffffu, mx1, 1));
    mx1 = fmaxf(mx1, __shfl_xor_sync(0xffffffffu, mx1, 2));

    float s0 = 0.0f, s1 = 0.0f;
#pragma unroll
    for (int nt = 0; nt < 8; ++nt) {
        cc[nt][0] = __expf(cc[nt][0] - mx0);
        cc[nt][1] = __expf(cc[nt][1] - mx0);
        cc[nt][2] = __expf(cc[nt][2] - mx1);
        cc[nt][3] = __expf(cc[nt][3] - mx1);
        s0 += cc[nt][0] + cc[nt][1];
        s1 += cc[nt][2] + cc[nt][3];
    }
    s0 += __shfl_xor_sync(0xffffffffu, s0, 1);
    s0 += __shfl_xor_sync(0xffffffffu, s0, 2);
    s1 += __shfl_xor_sync(0xffffffffu, s1, 1);
    s1 += __shfl_xor_sync(0xffffffffu, s1, 2);
    const float inv0 = 1.0f / s0;
    const float inv1 = 1.0f / s1;

    unsigned* psw = ps[wt];
#pragma unroll
    for (int nt = 0; nt < 8; ++nt) {
        psw[g * 36 + nt * 4 + t]       = pkh(cc[nt][0], cc[nt][1]);
        psw[(g + 8) * 36 + nt * 4 + t] = pkh(cc[nt][2], cc[nt][3]);
    }
    __syncwarp();

    const unsigned ps_b  = (unsigned)__cvta_generic_to_shared(ps[wt]);
    const unsigned vts_b = (unsigned)__cvta_generic_to_shared(vts);
    float out[4][4];
#pragma unroll
    for (int vt = 0; vt < 4; ++vt)
#pragma unroll
        for (int q = 0; q < 4; ++q) out[vt][q] = 0.0f;

#pragma unroll
    for (int kb = 0; kb < 4; ++kb) {
        unsigned a4[4];
        ldsm4(a4, ps_b + alm * 144 + kb * 32 + alk);
#pragma unroll
        for (int vtp = 0; vtp < 2; ++vtp) {
            unsigned b4[4];
            ldsm4(b4, vts_b + (vtp * 16 + blm) * 144 + kb * 32 + blk);
            mma16(out[2 * vtp],     a4, b4);
            mma16(out[2 * vtp + 1], a4, b4 + 2);
        }
    }

    const int d0i = (((w << 6) | r0) << 8) + h * 32;
    const int d1i = (((w << 6) | r1) << 8) + h * 32;
    unsigned* ao32 = (unsigned*)g_ao;
#pragma unroll
    for (int vt = 0; vt < 4; ++vt) {
        ao32[(d0i + vt * 8 + 2 * t) >> 1] = pkh(out[vt][0] * inv0, out[vt][1] * inv0);
        ao32[(d1i + vt * 8 + 2 * t) >> 1] = pkh(out[vt][2] * inv1, out[vt][3] * inv1);
    }
}

// ============================================================
// Kernel 3: output projection fp16 + ldmatrix + inverse window/roll scatter.
// ============================================================
__global__ void __launch_bounds__(512)
swin_proj_kernel(const float* __restrict__ bo, float* __restrict__ out)
{
    extern __shared__ char smem[];
    const unsigned sb = (unsigned)__cvta_generic_to_shared(smem);
    float* bias_s = (float*)(smem + SM_BIAS);

    const int bw   = blockIdx.x;
    const int tid  = threadIdx.x;
    const int warp = tid >> 5;
    const int lane = tid & 31;
    const int g    = lane >> 2;
    const int t    = lane & 3;
    const int mw   = warp >> 2;
    const int nq   = warp & 3;

    const unsigned alm = lane & 15;
    const unsigned alk = (lane >> 4) << 4;
    const unsigned blm = (lane & 7) + ((lane >> 4) << 3);
    const unsigned blk = ((lane >> 3) & 1) << 4;

    if (tid < 256) bias_s[tid] = bo[tid];
    __syncthreads();

    const int srow = tid >> 3;
    const int sjj  = tid & 7;
    const unsigned asto0 = srow * 144 + sjj * 16;
    const unsigned asto1 = (srow + 64) * 144 + sjj * 16;
    const unsigned short* wh = g_wh + 3 * 65536;
    const int abase = bw * 128 * 256;

#define STAGE(c_, st_) do {                                                    \
        unsigned _a = sb + SM_BUF + (st_) * STG_BYTES;                         \
        cp16(_a + asto0, g_ao + abase + srow * 256 + (c_) * 64 + sjj * 8);     \
        cp16(_a + asto1, g_ao + abase + (srow + 64) * 256 + (c_) * 64 + sjj * 8); \
        unsigned _bB = _a + A_BYTES;                                           \
        _Pragma("unroll")                                                      \
        for (int _i = 0; _i < 4; ++_i) {                                       \
            int _n = srow + _i * 64;                                           \
            cp16(_bB + _n * 144 + sjj * 16, wh + _n * 256 + (c_) * 64 + sjj * 8); \
        }                                                                      \
        cp_commit();                                                           \
    } while (0)

    STAGE(0, 0);
    STAGE(1, 1);

    float acc[2][8][4];
#pragma unroll
    for (int mt = 0; mt < 2; ++mt)
#pragma unroll
        for (int nt = 0; nt < 8; ++nt)
#pragma unroll
            for (int q = 0; q < 4; ++q) acc[mt][nt][q] = 0.0f;

#pragma unroll 1
    for (int c = 0; c < 4; ++c) {
        const int st = c % 3;
        if (c == 3) cp_wait<0>(); else cp_wait<1>();
        __syncthreads();
        if (c + 2 < 4) STAGE(c + 2, (c + 2) % 3);

        const unsigned sbX = sb + SM_BUF + st * STG_BYTES;
        const unsigned sbB = sbX + A_BYTES;
#pragma unroll
        for (int ks = 0; ks < 4; ++ks) {
            unsigned a[2][4];
            ldsm4(a[0], sbX + (mw * 32 + alm) * 144 + ks * 32 + alk);
            ldsm4(a[1], sbX + (mw * 32 + 16 + alm) * 144 + ks * 32 + alk);
#pragma unroll
            for (int ntp = 0; ntp < 4; ++ntp) {
                unsigned b4[4];
                ldsm4(b4, sbB + (nq * 64 + ntp * 16 + blm) * 144 + ks * 32 + blk);
                mma16(acc[0][2 * ntp],     a[0], b4);
                mma16(acc[0][2 * ntp + 1], a[0], b4 + 2);
                mma16(acc[1][2 * ntp],     a[1], b4);
                mma16(acc[1][2 * ntp + 1], a[1], b4 + 2);
            }
        }
        __syncthreads();
    }
#undef STAGE

    float2 bb[8];
#pragma unroll
    for (int nt = 0; nt < 8; ++nt)
        bb[nt] = *(float2*)(bias_s + nq * 64 + nt * 8 + 2 * t);

#pragma unroll
    for (int mt = 0; mt < 2; ++mt)
#pragma unroll
        for (int rh = 0; rh < 2; ++rh)
#pragma unroll
            for (int nt = 0; nt < 8; ++nt) {
                int n   = mw * 32 + mt * 16 + rh * 8 + g;
                int wv  = bw * 2 + (n >> 6);
                int tok = n & 63;
                int b   = wv >> 6, wy = (wv >> 3) & 7, wx = wv & 7;
                int y   = ((wy << 3) + (tok >> 3) + 4) & 63;
                int xc  = ((wx << 3) + (tok & 7) + 4) & 63;
                int col = nq * 64 + nt * 8 + 2 * t;
                *(float2*)(out + (((b << 6) | y) << 14) + (xc << 8) + col) =
                    make_float2(acc[mt][nt][rh * 2] + bb[nt].x,
                                acc[mt][nt][rh * 2 + 1] + bb[nt].y);
            }
}

// ============================================================
extern "C" void kernel_launch(void* const* d_in, const int* in_sizes, int n_in,
                              void* d_out, int out_size)
{
    const float* x  = (const float*)d_in[0];
    const float* Wq = (const float*)d_in[1];
    const float* bq = (const float*)d_in[2];
    const float* Wk = (const float*)d_in[3];
    const float* bk = (const float*)d_in[4];
    const float* Wv = (const float*)d_in[5];
    const float* bv = (const float*)d_in[6];
    const float* Wo = (const float*)d_in[7];
    const float* bo = (const float*)d_in[8];
    const float* ls = (const float*)d_in[9];
    const float* w1 = (const float*)d_in[10];
    const float* b1 = (const float*)d_in[11];
    const float* w2 = (const float*)d_in[12];
    float* out = (float*)d_out;

    cudaFuncSetAttribute(swin_qkv_kernel,
                         cudaFuncAttributeMaxDynamicSharedMemorySize, G_SMEM);
    cudaFuncSetAttribute(swin_proj_kernel,
                         cudaFuncAttributeMaxDynamicSharedMemorySize, G_SMEM);

    swin_bias_kernel<<<225, 512>>>(ls, w1, b1, w2);
    swin_cvt_kernel<<<16640, 256>>>(x, Wq, Wk, Wv, Wo);
    swin_qkv_kernel<<<dim3(512, 3), 512, G_SMEM>>>(bq, bk, bv);
    swin_attn_kernel<<<dim3(NWIN, NHEAD), 128>>>();
    swin_proj_kernel<<<512, 512, G_SMEM>>>(bo, out);
}

// round 13
// speedup vs baseline: 1.3864x; 1.0195x over previous
#include <cuda_runtime.h>
#include <cuda_fp16.h>

// SwinV2 shifted-window attention, B=16, H=W=64, C=256, heads=8, hd=32.
// Round 13: round-12 structure with FULL-PREFETCH GEMM pipelines: all 4
// K-chunks staged via cp.async up front (4 resident stages, 225 KB smem),
// compute loop = wait + one sync + MMAs. Halves barriers, removes load
// issue from the critical path. Attention/cvt/bias identical to round 12.

#define NWIN   1024
#define NTOK   64
#define CDIM   256
#define NHEAD  8
#define HD     32

// -------- scratch (device globals; no allocation) --------
__device__ unsigned       g_qh [NWIN * NHEAD * NTOK * 16];   // q hi f16x2 words
__device__ unsigned       g_ql [NWIN * NHEAD * NTOK * 16];   // q lo
__device__ unsigned       g_kh [NWIN * NHEAD * NTOK * 16];   // k hi
__device__ unsigned       g_kl [NWIN * NHEAD * NTOK * 16];   // k lo
__device__ unsigned       g_v16[NWIN * NHEAD * NTOK * 16];   // v f16x2 words
__device__ unsigned short g_ao [NWIN * NTOK * CDIM];         // attn out fp16
__device__ unsigned short g_xh [16 * 64 * 64 * CDIM];        // x fp16
__device__ unsigned short g_wh [4 * CDIM * CDIM];            // W^T fp16 [n][k]
__device__ float          g_bias16[NHEAD * 225];
__device__ float          g_scale[NHEAD];

// -------- helpers --------
__device__ __forceinline__ unsigned pkh(float lo, float hi) {
    unsigned r;
    asm("cvt.rn.f16x2.f32 %0, %1, %2;" : "=r"(r) : "f"(hi), "f"(lo));
    return r;
}
__device__ __forceinline__ void mma16(float* c, const unsigned* a, const unsigned* b) {
    asm volatile("mma.sync.aligned.m16n8k16.row.col.f32.f16.f16.f32 "
                 "{%0,%1,%2,%3},{%4,%5,%6,%7},{%8,%9},{%0,%1,%2,%3};"
                 : "+f"(c[0]), "+f"(c[1]), "+f"(c[2]), "+f"(c[3])
                 : "r"(a[0]), "r"(a[1]), "r"(a[2]), "r"(a[3]),
                   "r"(b[0]), "r"(b[1]));
}
__device__ __forceinline__ void ldsm4(unsigned* r, unsigned addr) {
    asm volatile("ldmatrix.sync.aligned.m8n8.x4.shared.b16 {%0,%1,%2,%3}, [%4];"
                 : "=r"(r[0]), "=r"(r[1]), "=r"(r[2]), "=r"(r[3]) : "r"(addr));
}
__device__ __forceinline__ void cp16(unsigned dst, const void* src) {
    asm volatile("cp.async.cg.shared.global [%0], [%1], 16;" :: "r"(dst), "l"(src));
}
__device__ __forceinline__ void cp_commit() {
    asm volatile("cp.async.commit_group;");
}
template<int N> __device__ __forceinline__ void cp_wait() {
    asm volatile("cp.async.wait_group %0;" :: "n"(N));
}

// -------- fp16 GEMM smem geometry: 4 resident stages --------
#define A_BYTES   (128 * 144)
#define STG_BYTES (A_BYTES + 256 * 144)      // 55296
#define SM_ROWB   64
#define SM_BIAS   1024
#define SM_BUF    4096
#define G_SMEM    (SM_BUF + 4 * STG_BYTES)   // 225280

// ============================================================
// Kernel 0: continuous-position-bias MLP
// ============================================================
__global__ void swin_bias_kernel(const float* __restrict__ ls,
                                 const float* __restrict__ w1,
                                 const float* __restrict__ b1,
                                 const float* __restrict__ w2)
{
    __shared__ float part[16][8];
    const int t   = blockIdx.x;
    const int i   = t / 15;
    const int j   = t % 15;
    const int tid = threadIdx.x;
    const int warp = tid >> 5;
    const int lane = tid & 31;

    float rh = (float)(i - 7) * (8.0f / 7.0f);
    float rw = (float)(j - 7) * (8.0f / 7.0f);
    rh = copysignf(log2f(fabsf(rh) + 1.0f) * (1.0f / 3.0f), rh);
    rw = copysignf(log2f(fabsf(rw) + 1.0f) * (1.0f / 3.0f), rw);

    float hv = fmaxf(0.0f, rh * w1[tid] + rw * w1[512 + tid] + b1[tid]);

    float p[8];
#pragma unroll
    for (int h = 0; h < 8; ++h) p[h] = hv * w2[tid * 8 + h];
#pragma unroll
    for (int off = 16; off; off >>= 1)
#pragma unroll
        for (int h = 0; h < 8; ++h) p[h] += __shfl_xor_sync(0xffffffffu, p[h], off);
    if (lane == 0)
#pragma unroll
        for (int h = 0; h < 8; ++h) part[warp][h] = p[h];
    __syncthreads();

    if (tid < 8) {
        float s = 0.0f;
#pragma unroll
        for (int g = 0; g < 16; ++g) s += part[g][tid];
        g_bias16[tid * 225 + t] = 16.0f / (1.0f + expf(-s));
    }
    if (blockIdx.x == 0 && tid < 8)
        g_scale[tid] = expf(fminf(ls[tid], 4.6051701860f));
}

// ============================================================
// Kernel 0b: x -> fp16; W -> transposed fp16 [n][k]
// ============================================================
__global__ void swin_cvt_kernel(const float* __restrict__ x,
                                const float* __restrict__ Wq,
                                const float* __restrict__ Wk,
                                const float* __restrict__ Wv,
                                const float* __restrict__ Wo)
{
    const int blk = blockIdx.x;
    const int tid = threadIdx.x;
    if (blk < 16384) {
        int i4 = blk * 256 + tid;
        float4 v = ((const float4*)x)[i4];
        ((uint2*)g_xh)[i4] = make_uint2(pkh(v.x, v.y), pkh(v.z, v.w));
    } else {
        int r = blk - 16384;
        int m = r >> 6;
        const float* W = (m == 0) ? Wq : (m == 1) ? Wk : (m == 2) ? Wv : Wo;
        int idx = (r & 63) * 256 + tid;
        int n  = idx >> 6;
        int k4 = (idx & 63) * 4;
        float a0 = W[(k4 + 0) * 256 + n];
        float a1 = W[(k4 + 1) * 256 + n];
        float a2 = W[(k4 + 2) * 256 + n];
        float a3 = W[(k4 + 3) * 256 + n];
        ((uint2*)(g_wh + m * 65536))[idx] = make_uint2(pkh(a0, a1), pkh(a2, a3));
    }
}

// ============================================================
// Kernel 1: one QKV matrix per CTA. grid (512, 3): y = 0:Q, 1:K, 2:V.
// M=128, N=256, K=256 in 4 chunks, ALL chunks prefetched up front.
// ============================================================
__global__ void __launch_bounds__(512)
swin_qkv_kernel(const float* __restrict__ bq,
                const float* __restrict__ bk,
                const float* __restrict__ bv)
{
    extern __shared__ char smem[];
    const unsigned sb = (unsigned)__cvta_generic_to_shared(smem);
    unsigned* rowb_s = (unsigned*)(smem + SM_ROWB);
    float*    bias_s = (float*)(smem + SM_BIAS);

    const int bw   = blockIdx.x;
    const int m    = blockIdx.y;          // 0=Q, 1=K, 2=V
    const int tid  = threadIdx.x;
    const int warp = tid >> 5;
    const int lane = tid & 31;
    const int g    = lane >> 2;
    const int t    = lane & 3;
    const int mw   = warp >> 2;
    const int nq   = warp & 3;

    const unsigned alm = lane & 15;
    const unsigned alk = (lane >> 4) << 4;
    const unsigned blm = (lane & 7) + ((lane >> 4) << 3);
    const unsigned blk = ((lane >> 3) & 1) << 4;

    if (tid < 128) {
        int wv = bw * 2 + (tid >> 6);
        int b = wv >> 6, wy = (wv >> 3) & 7, wx = wv & 7;
        int tok = tid & 63;
        int sy = ((wy << 3) + (tok >> 3) + 4) & 63;
        int sx = ((wx << 3) + (tok & 7) + 4) & 63;
        rowb_s[tid] = ((((b << 6) | sy) << 6) | sx) << 8;
    }
    if (tid < 256) {
        const float* bp = (m == 0) ? bq : (m == 1) ? bk : bv;
        bias_s[tid] = bp[tid];
    }
    __syncthreads();

    const int srow = tid >> 3;
    const int sjj  = tid & 7;
    const unsigned rb0 = rowb_s[srow];
    const unsigned rb1 = rowb_s[srow + 64];
    const unsigned asto0 = srow * 144 + sjj * 16;
    const unsigned asto1 = (srow + 64) * 144 + sjj * 16;
    const unsigned short* wh = g_wh + m * 65536;

#define STAGE(c_) do {                                                         \
        unsigned _a = sb + SM_BUF + (c_) * STG_BYTES;                          \
        cp16(_a + asto0, g_xh + rb0 + (c_) * 64 + sjj * 8);                    \
        cp16(_a + asto1, g_xh + rb1 + (c_) * 64 + sjj * 8);                    \
        unsigned _bB = _a + A_BYTES;                                           \
        _Pragma("unroll")                                                      \
        for (int _i = 0; _i < 4; ++_i) {                                       \
            int _n = srow + _i * 64;                                           \
            cp16(_bB + _n * 144 + sjj * 16, wh + _n * 256 + (c_) * 64 + sjj * 8); \
        }                                                                      \
        cp_commit();                                                           \
    } while (0)

    STAGE(0); STAGE(1); STAGE(2); STAGE(3);

    float acc[2][8][4];
#pragma unroll
    for (int mt = 0; mt < 2; ++mt)
#pragma unroll
        for (int nt = 0; nt < 8; ++nt)
#pragma unroll
            for (int q = 0; q < 4; ++q) acc[mt][nt][q] = 0.0f;

#pragma unroll 1
    for (int c = 0; c < 4; ++c) {
        if      (c == 0) cp_wait<3>();
        else if (c == 1) cp_wait<2>();
        else if (c == 2) cp_wait<1>();
        else             cp_wait<0>();
        __syncthreads();

        const unsigned sbX = sb + SM_BUF + c * STG_BYTES;
        const unsigned sbB = sbX + A_BYTES;
#pragma unroll
        for (int ks = 0; ks < 4; ++ks) {
            unsigned a[2][4];
            ldsm4(a[0], sbX + (mw * 32 + alm) * 144 + ks * 32 + alk);
            ldsm4(a[1], sbX + (mw * 32 + 16 + alm) * 144 + ks * 32 + alk);
#pragma unroll
            for (int ntp = 0; ntp < 4; ++ntp) {
                unsigned b4[4];
                ldsm4(b4, sbB + (nq * 64 + ntp * 16 + blm) * 144 + ks * 32 + blk);
                mma16(acc[0][2 * ntp],     a[0], b4);
                mma16(acc[0][2 * ntp + 1], a[0], b4 + 2);
                mma16(acc[1][2 * ntp],     a[1], b4);
                mma16(acc[1][2 * ntp + 1], a[1], b4 + 2);
            }
        }
    }
#undef STAGE

    // ---- epilogue ----
    float2 bb[8];
#pragma unroll
    for (int nt = 0; nt < 8; ++nt)
        bb[nt] = *(float2*)(bias_s + nq * 64 + nt * 8 + 2 * t);
#pragma unroll
    for (int mt = 0; mt < 2; ++mt)
#pragma unroll
        for (int nt = 0; nt < 8; ++nt) {
            acc[mt][nt][0] += bb[nt].x;  acc[mt][nt][1] += bb[nt].y;
            acc[mt][nt][2] += bb[nt].x;  acc[mt][nt][3] += bb[nt].y;
        }

    if (m < 2) {   // cosine normalization for Q and K
#pragma unroll
        for (int mt = 0; mt < 2; ++mt)
#pragma unroll
            for (int rh = 0; rh < 2; ++rh)
#pragma unroll
                for (int hh = 0; hh < 2; ++hh) {
                    float s = 0.0f;
#pragma unroll
                    for (int k2 = 0; k2 < 4; ++k2) {
                        int nt = hh * 4 + k2;
                        s += acc[mt][nt][rh * 2]     * acc[mt][nt][rh * 2]
                           + acc[mt][nt][rh * 2 + 1] * acc[mt][nt][rh * 2 + 1];
                    }
                    s += __shfl_xor_sync(0xffffffffu, s, 1);
                    s += __shfl_xor_sync(0xffffffffu, s, 2);
                    float inv = 1.0f / fmaxf(sqrtf(s), 1e-12f);
#pragma unroll
                    for (int k2 = 0; k2 < 4; ++k2) {
                        int nt = hh * 4 + k2;
                        acc[mt][nt][rh * 2]     *= inv;
                        acc[mt][nt][rh * 2 + 1] *= inv;
                    }
                }
    }

#pragma unroll
    for (int mt = 0; mt < 2; ++mt)
#pragma unroll
        for (int rh = 0; rh < 2; ++rh)
#pragma unroll
            for (int nt = 0; nt < 8; ++nt) {
                int n    = mw * 32 + mt * 16 + rh * 8 + g;
                int win  = bw * 2 + (n >> 6);
                int tok  = n & 63;
                int col  = nq * 64 + nt * 8 + 2 * t;
                int head = col >> 5;
                int d    = col & 31;
                int idx  = (((win << 3) | head) << 10) + (tok << 4) + (d >> 1);
                float vx = acc[mt][nt][rh * 2];
                float vy = acc[mt][nt][rh * 2 + 1];
                if (m == 2) {
                    g_v16[idx] = pkh(vx, vy);
                } else {
                    unsigned hw = pkh(vx, vy);
                    float2 hf = __half22float2(*(__half2*)&hw);
                    unsigned lw = pkh(vx - hf.x, vy - hf.y);
                    if (m == 0) { g_qh[idx] = hw; g_ql[idx] = lw; }
                    else        { g_kh[idx] = hw; g_kl[idx] = lw; }
                }
            }
}

// ============================================================
// Kernel 2: fully-fp16 MMA attention + ldmatrix (round 10/12).
// grid (1024, 8), 128 threads.
// ============================================================
__global__ void __launch_bounds__(128)
swin_attn_kernel()
{
    __shared__ __align__(16) unsigned khs[64 * 20];
    __shared__ __align__(16) unsigned kls[64 * 20];
    __shared__ __align__(16) unsigned vts[32 * 36];
    __shared__ __align__(16) unsigned ps[4][16 * 36];
    __shared__ float bs[228];

    const int w    = blockIdx.x;
    const int h    = blockIdx.y;
    const int tid  = threadIdx.x;
    const int wt   = tid >> 5;
    const int lane = tid & 31;
    const int g    = lane >> 2;
    const int t    = lane & 3;
    const int pbase = ((w << 3) | h) << 10;

    const unsigned alm = lane & 15;
    const unsigned alk = (lane >> 4) << 4;
    const unsigned blm = (lane & 7) + ((lane >> 4) << 3);
    const unsigned blk = ((lane >> 3) & 1) << 4;

    const uint4* khp4 = (const uint4*)(g_kh + pbase);
    const uint4* klp4 = (const uint4*)(g_kl + pbase);
#pragma unroll
    for (int it = 0; it < 2; ++it) {
        int i4  = tid + it * 128;
        int row = i4 >> 2;
        int c4  = (i4 & 3) << 2;
        *(uint4*)(khs + row * 20 + c4) = khp4[i4];
        *(uint4*)(kls + row * 20 + c4) = klp4[i4];
    }

    {
        const int mp = tid & 31;
        const int dp = tid >> 5;
        const uint4* v4 = (const uint4*)(g_v16 + pbase);
        uint4 a = v4[(2 * mp) * 4 + dp];
        uint4 b = v4[(2 * mp + 1) * 4 + dp];
        int d0 = dp * 8;
        vts[(d0 + 0) * 36 + mp] = __byte_perm(a.x, b.x, 0x5410);
        vts[(d0 + 1) * 36 + mp] = __byte_perm(a.x, b.x, 0x7632);
        vts[(d0 + 2) * 36 + mp] = __byte_perm(a.y, b.y, 0x5410);
        vts[(d0 + 3) * 36 + mp] = __byte_perm(a.y, b.y, 0x7632);
        vts[(d0 + 4) * 36 + mp] = __byte_perm(a.z, b.z, 0x5410);
        vts[(d0 + 5) * 36 + mp] = __byte_perm(a.z, b.z, 0x7632);
        vts[(d0 + 6) * 36 + mp] = __byte_perm(a.w, b.w, 0x5410);
        vts[(d0 + 7) * 36 + mp] = __byte_perm(a.w, b.w, 0x7632);
    }
    for (int i = tid; i < 225; i += 128) bs[i] = g_bias16[h * 225 + i];
    __syncthreads();

    const float sc = g_scale[h];
    const int wy = (w >> 3) & 7, wx = w & 7;
    const bool mhb = (wy == 7), mwb = (wx == 7);
    const int r0 = wt * 16 + g;
    const int r1 = r0 + 8;

    const unsigned* qhp = g_qh + pbase;
    const unsigned* qlp = g_ql + pbase;
    unsigned aqh[2][4], aql[2][4];
#pragma unroll
    for (int ks = 0; ks < 2; ++ks) {
        int bidx = r0 * 16 + ks * 8 + t;
        aqh[ks][0] = qhp[bidx];        aqh[ks][1] = qhp[bidx + 128];
        aqh[ks][2] = qhp[bidx + 4];    aqh[ks][3] = qhp[bidx + 132];
        aql[ks][0] = qlp[bidx];        aql[ks][1] = qlp[bidx + 128];
        aql[ks][2] = qlp[bidx + 4];    aql[ks][3] = qlp[bidx + 132];
    }

    const unsigned khs_b = (unsigned)__cvta_generic_to_shared(khs);
    const unsigned kls_b = (unsigned)__cvta_generic_to_shared(kls);
    float cc[8][4];
#pragma unroll
    for (int nt = 0; nt < 8; ++nt)
#pragma unroll
        for (int q = 0; q < 4; ++q) cc[nt][q] = 0.0f;

#pragma unroll
    for (int ks = 0; ks < 2; ++ks) {
#pragma unroll
        for (int ntp = 0; ntp < 4; ++ntp) {
            unsigned off = (ntp * 16 + blm) * 80 + ks * 32 + blk;
            unsigned rh4[4], rl4[4];
            ldsm4(rh4, khs_b + off);
            ldsm4(rl4, kls_b + off);
            mma16(cc[2 * ntp],     aqh[ks], rh4);
            mma16(cc[2 * ntp],     aql[ks], rh4);
            mma16(cc[2 * ntp],     aqh[ks], rl4);
            mma16(cc[2 * ntp + 1], aqh[ks], rh4 + 2);
            mma16(cc[2 * ntp + 1], aql[ks], rh4 + 2);
            mma16(cc[2 * ntp + 1], aqh[ks], rl4 + 2);
        }
    }

    const int ty0 = r0 >> 3, tx0 = r0 & 7;
    const int ty1 = r1 >> 3, tx1 = r1 & 7;
#pragma unroll
    for (int nt = 0; nt < 8; ++nt)
#pragma unroll
        for (int q = 0; q < 4; ++q) {
            int m  = nt * 8 + 2 * t + (q & 1);
            int my = m >> 3, mxc = m & 7;
            int ty = (q < 2) ? ty0 : ty1;
            int tx = (q < 2) ? tx0 : tx1;
            float v = cc[nt][q] * sc + bs[(ty - my + 7) * 15 + (tx - mxc + 7)];
            if (mhb && ((ty < 4) != (my < 4)))  v -= 100.0f;
            if (mwb && ((tx < 4) != (mxc < 4))) v -= 100.0f;
            cc[nt][q] = v;
        }

    float mx0 = -1e30f, mx1 = -1e30f;
#pragma unroll
    for (int nt = 0; nt < 8; ++nt) {
        mx0 = fmaxf(mx0, fmaxf(cc[nt][0], cc[nt][1]));
        mx1 = fmaxf(mx1, fmaxf(cc[nt][2], cc[nt][3]));
    }
    mx0 = fmaxf(mx0, __shfl_xor_sync(0xffffffffu, mx0, 1));
    mx0 = fmaxf(mx0, __shfl_xor_sync(0xffffffffu, mx0, 2));
    mx1 = fmaxf(mx1, __shfl_xor_sync(0xffffffffu, mx1, 1));
    mx1 = fmaxf(mx1, __shfl_xor_sync(0xffffffffu, mx1, 2));

    float s0 = 0.0f, s1 = 0.0f;
#pragma unroll
    for (int nt = 0; nt < 8; ++nt) {
        cc[nt][0] = __expf(cc[nt][0] - mx0);
        cc[nt][1] = __expf(cc[nt][1] - mx0);
        cc[nt][2] = __expf(cc[nt][2] - mx1);
        cc[nt][3] = __expf(cc[nt][3] - mx1);
        s0 += cc[nt][0] + cc[nt][1];
        s1 += cc[nt][2] + cc[nt][3];
    }
    s0 += __shfl_xor_sync(0xffffffffu, s0, 1);
    s0 += __shfl_xor_sync(0xffffffffu, s0, 2);
    s1 += __shfl_xor_sync(0xffffffffu, s1, 1);
    s1 += __shfl_xor_sync(0xffffffffu, s1, 2);
    const float inv0 = 1.0f / s0;
    const float inv1 = 1.0f / s1;

    unsigned* psw = ps[wt];
#pragma unroll
    for (int nt = 0; nt < 8; ++nt) {
        psw[g * 36 + nt * 4 + t]       = pkh(cc[nt][0], cc[nt][1]);
        psw[(g + 8) * 36 + nt * 4 + t] = pkh(cc[nt][2], cc[nt][3]);
    }
    __syncwarp();

    const unsigned ps_b  = (unsigned)__cvta_generic_to_shared(ps[wt]);
    const unsigned vts_b = (unsigned)__cvta_generic_to_shared(vts);
    float out[4][4];
#pragma unroll
    for (int vt = 0; vt < 4; ++vt)
#pragma unroll
        for (int q = 0; q < 4; ++q) out[vt][q] = 0.0f;

#pragma unroll
    for (int kb = 0; kb < 4; ++kb) {
        unsigned a4[4];
        ldsm4(a4, ps_b + alm * 144 + kb * 32 + alk);
#pragma unroll
        for (int vtp = 0; vtp < 2; ++vtp) {
            unsigned b4[4];
            ldsm4(b4, vts_b + (vtp * 16 + blm) * 144 + kb * 32 + blk);
            mma16(out[2 * vtp],     a4, b4);
            mma16(out[2 * vtp + 1], a4, b4 + 2);
        }
    }

    const int d0i = (((w << 6) | r0) << 8) + h * 32;
    const int d1i = (((w << 6) | r1) << 8) + h * 32;
    unsigned* ao32 = (unsigned*)g_ao;
#pragma unroll
    for (int vt = 0; vt < 4; ++vt) {
        ao32[(d0i + vt * 8 + 2 * t) >> 1] = pkh(out[vt][0] * inv0, out[vt][1] * inv0);
        ao32[(d1i + vt * 8 + 2 * t) >> 1] = pkh(out[vt][2] * inv1, out[vt][3] * inv1);
    }
}

// ============================================================
// Kernel 3: output projection, full-prefetch 4-stage + scatter.
// ============================================================
__global__ void __launch_bounds__(512)
swin_proj_kernel(const float* __restrict__ bo, float* __restrict__ out)
{
    extern __shared__ char smem[];
    const unsigned sb = (unsigned)__cvta_generic_to_shared(smem);
    float* bias_s = (float*)(smem + SM_BIAS);

    const int bw   = blockIdx.x;
    const int tid  = threadIdx.x;
    const int warp = tid >> 5;
    const int lane = tid & 31;
    const int g    = lane >> 2;
    const int t    = lane & 3;
    const int mw   = warp >> 2;
    const int nq   = warp & 3;

    const unsigned alm = lane & 15;
    const unsigned alk = (lane >> 4) << 4;
    const unsigned blm = (lane & 7) + ((lane >> 4) << 3);
    const unsigned blk = ((lane >> 3) & 1) << 4;

    if (tid < 256) bias_s[tid] = bo[tid];
    __syncthreads();

    const int srow = tid >> 3;
    const int sjj  = tid & 7;
    const unsigned asto0 = srow * 144 + sjj * 16;
    const unsigned asto1 = (srow + 64) * 144 + sjj * 16;
    const unsigned short* wh = g_wh + 3 * 65536;
    const int abase = bw * 128 * 256;

#define STAGE(c_) do {                                                         \
        unsigned _a = sb + SM_BUF + (c_) * STG_BYTES;                          \
        cp16(_a + asto0, g_ao + abase + srow * 256 + (c_) * 64 + sjj * 8);     \
        cp16(_a + asto1, g_ao + abase + (srow + 64) * 256 + (c_) * 64 + sjj * 8); \
        unsigned _bB = _a + A_BYTES;                                           \
        _Pragma("unroll")                                                      \
        for (int _i = 0; _i < 4; ++_i) {                                       \
            int _n = srow + _i * 64;                                           \
            cp16(_bB + _n * 144 + sjj * 16, wh + _n * 256 + (c_) * 64 + sjj * 8); \
        }                                                                      \
        cp_commit();                                                           \
    } while (0)

    STAGE(0); STAGE(1); STAGE(2); STAGE(3);

    float acc[2][8][4];
#pragma unroll
    for (int mt = 0; mt < 2; ++mt)
#pragma unroll
        for (int nt = 0; nt < 8; ++nt)
#pragma unroll
            for (int q = 0; q < 4; ++q) acc[mt][nt][q] = 0.0f;

#pragma unroll 1
    for (int c = 0; c < 4; ++c) {
        if      (c == 0) cp_wait<3>();
        else if (c == 1) cp_wait<2>();
        else if (c == 2) cp_wait<1>();
        else             cp_wait<0>();
        __syncthreads();

        const unsigned sbX = sb + SM_BUF + c * STG_BYTES;
        const unsigned sbB = sbX + A_BYTES;
#pragma unroll
        for (int ks = 0; ks < 4; ++ks) {
            unsigned a[2][4];
            ldsm4(a[0], sbX + (mw * 32 + alm) * 144 + ks * 32 + alk);
            ldsm4(a[1], sbX + (mw * 32 + 16 + alm) * 144 + ks * 32 + alk);
#pragma unroll
            for (int ntp = 0; ntp < 4; ++ntp) {
                unsigned b4[4];
                ldsm4(b4, sbB + (nq * 64 + ntp * 16 + blm) * 144 + ks * 32 + blk);
                mma16(acc[0][2 * ntp],     a[0], b4);
                mma16(acc[0][2 * ntp + 1], a[0], b4 + 2);
                mma16(acc[1][2 * ntp],     a[1], b4);
                mma16(acc[1][2 * ntp + 1], a[1], b4 + 2);
            }
        }
    }
#undef STAGE

    float2 bb[8];
#pragma unroll
    for (int nt = 0; nt < 8; ++nt)
        bb[nt] = *(float2*)(bias_s + nq * 64 + nt * 8 + 2 * t);

#pragma unroll
    for (int mt = 0; mt < 2; ++mt)
#pragma unroll
        for (int rh = 0; rh < 2; ++rh)
#pragma unroll
            for (int nt = 0; nt < 8; ++nt) {
                int n   = mw * 32 + mt * 16 + rh * 8 + g;
                int wv  = bw * 2 + (n >> 6);
                int tok = n & 63;
                int b   = wv >> 6, wy = (wv >> 3) & 7, wx = wv & 7;
                int y   = ((wy << 3) + (tok >> 3) + 4) & 63;
                int xc  = ((wx << 3) + (tok & 7) + 4) & 63;
                int col = nq * 64 + nt * 8 + 2 * t;
                *(float2*)(out + (((b << 6) | y) << 14) + (xc << 8) + col) =
                    make_float2(acc[mt][nt][rh * 2] + bb[nt].x,
                                acc[mt][nt][rh * 2 + 1] + bb[nt].y);
            }
}

// ============================================================
extern "C" void kernel_launch(void* const* d_in, const int* in_sizes, int n_in,
                              void* d_out, int out_size)
{
    const float* x  = (const float*)d_in[0];
    const float* Wq = (const float*)d_in[1];
    const float* bq = (const float*)d_in[2];
    const float* Wk = (const float*)d_in[3];
    const float* bk = (const float*)d_in[4];
    const float* Wv = (const float*)d_in[5];
    const float* bv = (const float*)d_in[6];
    const float* Wo = (const float*)d_in[7];
    const float* bo = (const float*)d_in[8];
    const float* ls = (const float*)d_in[9];
    const float* w1 = (const float*)d_in[10];
    const float* b1 = (const float*)d_in[11];
    const float* w2 = (const float*)d_in[12];
    float* out = (float*)d_out;

    cudaFuncSetAttribute(swin_qkv_kernel,
                         cudaFuncAttributeMaxDynamicSharedMemorySize, G_SMEM);
    cudaFuncSetAttribute(swin_proj_kernel,
                         cudaFuncAttributeMaxDynamicSharedMemorySize, G_SMEM);

    swin_bias_kernel<<<225, 512>>>(ls, w1, b1, w2);
    swin_cvt_kernel<<<16640, 256>>>(x, Wq, Wk, Wv, Wo);
    swin_qkv_kernel<<<dim3(512, 3), 512, G_SMEM>>>(bq, bk, bv);
    swin_attn_kernel<<<dim3(NWIN, NHEAD), 128>>>();
    swin_proj_kernel<<<512, 512, G_SMEM>>>(bo, out);
}

// round 14
// speedup vs baseline: 1.5032x; 1.0843x over previous
#include <cuda_runtime.h>
#include <cuda_fp16.h>

// SwinV2 shifted-window attention, B=16, H=W=64, C=256, heads=8, hd=32.
// Round 14: GEMM CTA tile halved to M128xN128 (warp tile M32xN32), 3-stage
// cp.async, 110 KB smem + 64-reg cap -> 2 CTAs/SM (8 warps/SMSP) to cover
// the ldsm->mma latency that capped round 13. qkv grid (1024,3), proj 1024.
// Attention/cvt/bias identical to round 13.

#define NWIN   1024
#define NTOK   64
#define CDIM   256
#define NHEAD  8
#define HD     32

// -------- scratch (device globals; no allocation) --------
__device__ unsigned       g_qh [NWIN * NHEAD * NTOK * 16];
__device__ unsigned       g_ql [NWIN * NHEAD * NTOK * 16];
__device__ unsigned       g_kh [NWIN * NHEAD * NTOK * 16];
__device__ unsigned       g_kl [NWIN * NHEAD * NTOK * 16];
__device__ unsigned       g_v16[NWIN * NHEAD * NTOK * 16];
__device__ unsigned short g_ao [NWIN * NTOK * CDIM];
__device__ unsigned short g_xh [16 * 64 * 64 * CDIM];
__device__ unsigned short g_wh [4 * CDIM * CDIM];
__device__ float          g_bias16[NHEAD * 225];
__device__ float          g_scale[NHEAD];

// -------- helpers --------
__device__ __forceinline__ unsigned pkh(float lo, float hi) {
    unsigned r;
    asm("cvt.rn.f16x2.f32 %0, %1, %2;" : "=r"(r) : "f"(hi), "f"(lo));
    return r;
}
__device__ __forceinline__ void mma16(float* c, const unsigned* a, const unsigned* b) {
    asm volatile("mma.sync.aligned.m16n8k16.row.col.f32.f16.f16.f32 "
                 "{%0,%1,%2,%3},{%4,%5,%6,%7},{%8,%9},{%0,%1,%2,%3};"
                 : "+f"(c[0]), "+f"(c[1]), "+f"(c[2]), "+f"(c[3])
                 : "r"(a[0]), "r"(a[1]), "r"(a[2]), "r"(a[3]),
                   "r"(b[0]), "r"(b[1]));
}
__device__ __forceinline__ void ldsm4(unsigned* r, unsigned addr) {
    asm volatile("ldmatrix.sync.aligned.m8n8.x4.shared.b16 {%0,%1,%2,%3}, [%4];"
                 : "=r"(r[0]), "=r"(r[1]), "=r"(r[2]), "=r"(r[3]) : "r"(addr));
}
__device__ __forceinline__ void cp16(unsigned dst, const void* src) {
    asm volatile("cp.async.cg.shared.global [%0], [%1], 16;" :: "r"(dst), "l"(src));
}
__device__ __forceinline__ void cp_commit() {
    asm volatile("cp.async.commit_group;");
}
template<int N> __device__ __forceinline__ void cp_wait() {
    asm volatile("cp.async.wait_group %0;" :: "n"(N));
}

// -------- halved-tile GEMM smem geometry: 3 resident stages, 2 CTAs/SM ----
#define HA_BYTES  (128 * 144)                // 18432
#define HSTG      (2 * HA_BYTES)             // 36864 (A half + B half)
#define H_ROWB    0                          // 128 u32
#define H_BIAS    512                        // 256 f32
#define H_BUF     2048
#define H_SMEM    (H_BUF + 3 * HSTG)         // 112640

// ============================================================
// Kernel 0: continuous-position-bias MLP
// ============================================================
__global__ void swin_bias_kernel(const float* __restrict__ ls,
                                 const float* __restrict__ w1,
                                 const float* __restrict__ b1,
                                 const float* __restrict__ w2)
{
    __shared__ float part[16][8];
    const int t   = blockIdx.x;
    const int i   = t / 15;
    const int j   = t % 15;
    const int tid = threadIdx.x;
    const int warp = tid >> 5;
    const int lane = tid & 31;

    float rh = (float)(i - 7) * (8.0f / 7.0f);
    float rw = (float)(j - 7) * (8.0f / 7.0f);
    rh = copysignf(log2f(fabsf(rh) + 1.0f) * (1.0f / 3.0f), rh);
    rw = copysignf(log2f(fabsf(rw) + 1.0f) * (1.0f / 3.0f), rw);

    float hv = fmaxf(0.0f, rh * w1[tid] + rw * w1[512 + tid] + b1[tid]);

    float p[8];
#pragma unroll
    for (int h = 0; h < 8; ++h) p[h] = hv * w2[tid * 8 + h];
#pragma unroll
    for (int off = 16; off; off >>= 1)
#pragma unroll
        for (int h = 0; h < 8; ++h) p[h] += __shfl_xor_sync(0xffffffffu, p[h], off);
    if (lane == 0)
#pragma unroll
        for (int h = 0; h < 8; ++h) part[warp][h] = p[h];
    __syncthreads();

    if (tid < 8) {
        float s = 0.0f;
#pragma unroll
        for (int g = 0; g < 16; ++g) s += part[g][tid];
        g_bias16[tid * 225 + t] = 16.0f / (1.0f + expf(-s));
    }
    if (blockIdx.x == 0 && tid < 8)
        g_scale[tid] = expf(fminf(ls[tid], 4.6051701860f));
}

// ============================================================
// Kernel 0b: x -> fp16; W -> transposed fp16 [n][k]
// ============================================================
__global__ void swin_cvt_kernel(const float* __restrict__ x,
                                const float* __restrict__ Wq,
                                const float* __restrict__ Wk,
                                const float* __restrict__ Wv,
                                const float* __restrict__ Wo)
{
    const int blk = blockIdx.x;
    const int tid = threadIdx.x;
    if (blk < 16384) {
        int i4 = blk * 256 + tid;
        float4 v = ((const float4*)x)[i4];
        ((uint2*)g_xh)[i4] = make_uint2(pkh(v.x, v.y), pkh(v.z, v.w));
    } else {
        int r = blk - 16384;
        int m = r >> 6;
        const float* W = (m == 0) ? Wq : (m == 1) ? Wk : (m == 2) ? Wv : Wo;
        int idx = (r & 63) * 256 + tid;
        int n  = idx >> 6;
        int k4 = (idx & 63) * 4;
        float a0 = W[(k4 + 0) * 256 + n];
        float a1 = W[(k4 + 1) * 256 + n];
        float a2 = W[(k4 + 2) * 256 + n];
        float a3 = W[(k4 + 3) * 256 + n];
        ((uint2*)(g_wh + m * 65536))[idx] = make_uint2(pkh(a0, a1), pkh(a2, a3));
    }
}

// ============================================================
// Kernel 1: QKV. grid (1024, 3): x = bw*2+nh, y = 0:Q,1:K,2:V.
// CTA: M=128 (2 windows) x N=128 (half). 16 warps, warp tile M32xN32.
// 3-stage cp.async over 4 K-chunks; 2 CTAs/SM.
// ============================================================
__global__ void __launch_bounds__(512, 2)
swin_qkv_kernel(const float* __restrict__ bq,
                const float* __restrict__ bk,
                const float* __restrict__ bv)
{
    extern __shared__ char smem[];
    const unsigned sb = (unsigned)__cvta_generic_to_shared(smem);
    unsigned* rowb_s = (unsigned*)(smem + H_ROWB);
    float*    bias_s = (float*)(smem + H_BIAS);

    const int bx   = blockIdx.x;
    const int bw   = bx >> 1;
    const int nh   = bx & 1;
    const int m    = blockIdx.y;
    const int tid  = threadIdx.x;
    const int warp = tid >> 5;
    const int lane = tid & 31;
    const int g    = lane >> 2;
    const int t    = lane & 3;
    const int mw   = warp >> 2;           // M 32-slice
    const int nq   = warp & 3;            // N 32-slice within half

    const unsigned alm = lane & 15;
    const unsigned alk = (lane >> 4) << 4;
    const unsigned blm = (lane & 7) + ((lane >> 4) << 3);
    const unsigned blk = ((lane >> 3) & 1) << 4;

    if (tid < 128) {
        int wv = bw * 2 + (tid >> 6);
        int b = wv >> 6, wy = (wv >> 3) & 7, wx = wv & 7;
        int tok = tid & 63;
        int sy = ((wy << 3) + (tok >> 3) + 4) & 63;
        int sx = ((wx << 3) + (tok & 7) + 4) & 63;
        rowb_s[tid] = ((((b << 6) | sy) << 6) | sx) << 8;
    }
    if (tid < 128) {
        const float* bp = (m == 0) ? bq : (m == 1) ? bk : bv;
        bias_s[tid] = bp[nh * 128 + tid];
    }
    __syncthreads();

    const int srow = tid >> 3;            // 0..63
    const int sjj  = tid & 7;
    const unsigned rb0 = rowb_s[srow];
    const unsigned rb1 = rowb_s[srow + 64];
    const unsigned sto0 = srow * 144 + sjj * 16;
    const unsigned sto1 = (srow + 64) * 144 + sjj * 16;
    const unsigned short* wh = g_wh + m * 65536 + (nh << 15);   // + nh*128 rows

#define STAGE(c_, st_) do {                                                    \
        unsigned _a = sb + H_BUF + (st_) * HSTG;                               \
        cp16(_a + sto0, g_xh + rb0 + (c_) * 64 + sjj * 8);                     \
        cp16(_a + sto1, g_xh + rb1 + (c_) * 64 + sjj * 8);                     \
        unsigned _bB = _a + HA_BYTES;                                          \
        cp16(_bB + sto0, wh + srow * 256 + (c_) * 64 + sjj * 8);               \
        cp16(_bB + sto1, wh + (srow + 64) * 256 + (c_) * 64 + sjj * 8);        \
        cp_commit();                                                           \
    } while (0)

    STAGE(0, 0); STAGE(1, 1); STAGE(2, 2);

    float acc[2][4][4];
#pragma unroll
    for (int mt = 0; mt < 2; ++mt)
#pragma unroll
        for (int nt = 0; nt < 4; ++nt)
#pragma unroll
            for (int q = 0; q < 4; ++q) acc[mt][nt][q] = 0.0f;

#pragma unroll 1
    for (int c = 0; c < 4; ++c) {
        if      (c == 0) cp_wait<2>();
        else if (c == 1) cp_wait<1>();
        else if (c == 2) cp_wait<1>();
        else             cp_wait<0>();
        __syncthreads();
        if (c == 1) STAGE(3, 0);          // stage 0 free after c=0 compute

        const unsigned sbX = sb + H_BUF + (c % 3) * HSTG;
        const unsigned sbB = sbX + HA_BYTES;
#pragma unroll
        for (int ks = 0; ks < 4; ++ks) {
            unsigned a[2][4];
            ldsm4(a[0], sbX + (mw * 32 + alm) * 144 + ks * 32 + alk);
            ldsm4(a[1], sbX + (mw * 32 + 16 + alm) * 144 + ks * 32 + alk);
#pragma unroll
            for (int ntp = 0; ntp < 2; ++ntp) {
                unsigned b4[4];
                ldsm4(b4, sbB + (nq * 32 + ntp * 16 + blm) * 144 + ks * 32 + blk);
                mma16(acc[0][2 * ntp],     a[0], b4);
                mma16(acc[0][2 * ntp + 1], a[0], b4 + 2);
                mma16(acc[1][2 * ntp],     a[1], b4);
                mma16(acc[1][2 * ntp + 1], a[1], b4 + 2);
            }
        }
    }
#undef STAGE

    // ---- epilogue: warp covers exactly one head ----
    const int head = nh * 4 + nq;
    float2 bb[4];
#pragma unroll
    for (int nt = 0; nt < 4; ++nt)
        bb[nt] = *(float2*)(bias_s + nq * 32 + nt * 8 + 2 * t);
#pragma unroll
    for (int mt = 0; mt < 2; ++mt)
#pragma unroll
        for (int nt = 0; nt < 4; ++nt) {
            acc[mt][nt][0] += bb[nt].x;  acc[mt][nt][1] += bb[nt].y;
            acc[mt][nt][2] += bb[nt].x;  acc[mt][nt][3] += bb[nt].y;
        }

    if (m < 2) {   // cosine normalization over the head's 32 dims
#pragma unroll
        for (int mt = 0; mt < 2; ++mt)
#pragma unroll
            for (int rh = 0; rh < 2; ++rh) {
                float s = 0.0f;
#pragma unroll
                for (int nt = 0; nt < 4; ++nt)
                    s += acc[mt][nt][rh * 2]     * acc[mt][nt][rh * 2]
                       + acc[mt][nt][rh * 2 + 1] * acc[mt][nt][rh * 2 + 1];
                s += __shfl_xor_sync(0xffffffffu, s, 1);
                s += __shfl_xor_sync(0xffffffffu, s, 2);
                float inv = 1.0f / fmaxf(sqrtf(s), 1e-12f);
#pragma unroll
                for (int nt = 0; nt < 4; ++nt) {
                    acc[mt][nt][rh * 2]     *= inv;
                    acc[mt][nt][rh * 2 + 1] *= inv;
                }
            }
    }

#pragma unroll
    for (int mt = 0; mt < 2; ++mt)
#pragma unroll
        for (int rh = 0; rh < 2; ++rh)
#pragma unroll
            for (int nt = 0; nt < 4; ++nt) {
                int n    = mw * 32 + mt * 16 + rh * 8 + g;
                int win  = bw * 2 + (n >> 6);
                int tok  = n & 63;
                int d    = nt * 8 + 2 * t;
                int idx  = (((win << 3) | head) << 10) + (tok << 4) + (d >> 1);
                float vx = acc[mt][nt][rh * 2];
                float vy = acc[mt][nt][rh * 2 + 1];
                if (m == 2) {
                    g_v16[idx] = pkh(vx, vy);
                } else {
                    unsigned hw = pkh(vx, vy);
                    float2 hf = __half22float2(*(__half2*)&hw);
                    unsigned lw = pkh(vx - hf.x, vy - hf.y);
                    if (m == 0) { g_qh[idx] = hw; g_ql[idx] = lw; }
                    else        { g_kh[idx] = hw; g_kl[idx] = lw; }
                }
            }
}

// ============================================================
// Kernel 2: fully-fp16 MMA attention + ldmatrix (round 13).
// grid (1024, 8), 128 threads.
// ============================================================
__global__ void __launch_bounds__(128)
swin_attn_kernel()
{
    __shared__ __align__(16) unsigned khs[64 * 20];
    __shared__ __align__(16) unsigned kls[64 * 20];
    __shared__ __align__(16) unsigned vts[32 * 36];
    __shared__ __align__(16) unsigned ps[4][16 * 36];
    __shared__ float bs[228];

    const int w    = blockIdx.x;
    const int h    = blockIdx.y;
    const int tid  = threadIdx.x;
    const int wt   = tid >> 5;
    const int lane = tid & 31;
    const int g    = lane >> 2;
    const int t    = lane & 3;
    const int pbase = ((w << 3) | h) << 10;

    const unsigned alm = lane & 15;
    const unsigned alk = (lane >> 4) << 4;
    const unsigned blm = (lane & 7) + ((lane >> 4) << 3);
    const unsigned blk = ((lane >> 3) & 1) << 4;

    const uint4* khp4 = (const uint4*)(g_kh + pbase);
    const uint4* klp4 = (const uint4*)(g_kl + pbase);
#pragma unroll
    for (int it = 0; it < 2; ++it) {
        int i4  = tid + it * 128;
        int row = i4 >> 2;
        int c4  = (i4 & 3) << 2;
        *(uint4*)(khs + row * 20 + c4) = khp4[i4];
        *(uint4*)(kls + row * 20 + c4) = klp4[i4];
    }

    {
        const int mp = tid & 31;
        const int dp = tid >> 5;
        const uint4* v4 = (const uint4*)(g_v16 + pbase);
        uint4 a = v4[(2 * mp) * 4 + dp];
        uint4 b = v4[(2 * mp + 1) * 4 + dp];
        int d0 = dp * 8;
        vts[(d0 + 0) * 36 + mp] = __byte_perm(a.x, b.x, 0x5410);
        vts[(d0 + 1) * 36 + mp] = __byte_perm(a.x, b.x, 0x7632);
        vts[(d0 + 2) * 36 + mp] = __byte_perm(a.y, b.y, 0x5410);
        vts[(d0 + 3) * 36 + mp] = __byte_perm(a.y, b.y, 0x7632);
        vts[(d0 + 4) * 36 + mp] = __byte_perm(a.z, b.z, 0x5410);
        vts[(d0 + 5) * 36 + mp] = __byte_perm(a.z, b.z, 0x7632);
        vts[(d0 + 6) * 36 + mp] = __byte_perm(a.w, b.w, 0x5410);
        vts[(d0 + 7) * 36 + mp] = __byte_perm(a.w, b.w, 0x7632);
    }
    for (int i = tid; i < 225; i += 128) bs[i] = g_bias16[h * 225 + i];
    __syncthreads();

    const float sc = g_scale[h];
    const int wy = (w >> 3) & 7, wx = w & 7;
    const bool mhb = (wy == 7), mwb = (wx == 7);
    const int r0 = wt * 16 + g;
    const int r1 = r0 + 8;

    const unsigned* qhp = g_qh + pbase;
    const unsigned* qlp = g_ql + pbase;
    unsigned aqh[2][4], aql[2][4];
#pragma unroll
    for (int ks = 0; ks < 2; ++ks) {
        int bidx = r0 * 16 + ks * 8 + t;
        aqh[ks][0] = qhp[bidx];        aqh[ks][1] = qhp[bidx + 128];
        aqh[ks][2] = qhp[bidx + 4];    aqh[ks][3] = qhp[bidx + 132];
        aql[ks][0] = qlp[bidx];        aql[ks][1] = qlp[bidx + 128];
        aql[ks][2] = qlp[bidx + 4];    aql[ks][3] = qlp[bidx + 132];
    }

    const unsigned khs_b = (unsigned)__cvta_generic_to_shared(khs);
    const unsigned kls_b = (unsigned)__cvta_generic_to_shared(kls);
    float cc[8][4];
#pragma unroll
    for (int nt = 0; nt < 8; ++nt)
#pragma unroll
        for (int q = 0; q < 4; ++q) cc[nt][q] = 0.0f;

#pragma unroll
    for (int ks = 0; ks < 2; ++ks) {
#pragma unroll
        for (int ntp = 0; ntp < 4; ++ntp) {
            unsigned off = (ntp * 16 + blm) * 80 + ks * 32 + blk;
            unsigned rh4[4], rl4[4];
            ldsm4(rh4, khs_b + off);
            ldsm4(rl4, kls_b + off);
            mma16(cc[2 * ntp],     aqh[ks], rh4);
            mma16(cc[2 * ntp],     aql[ks], rh4);
            mma16(cc[2 * ntp],     aqh[ks], rl4);
            mma16(cc[2 * ntp + 1], aqh[ks], rh4 + 2);
            mma16(cc[2 * ntp + 1], aql[ks], rh4 + 2);
            mma16(cc[2 * ntp + 1], aqh[ks], rl4 + 2);
        }
    }

    const int ty0 = r0 >> 3, tx0 = r0 & 7;
    const int ty1 = r1 >> 3, tx1 = r1 & 7;
#pragma unroll
    for (int nt = 0; nt < 8; ++nt)
#pragma unroll
        for (int q = 0; q < 4; ++q) {
            int m  = nt * 8 + 2 * t + (q & 1);
            int my = m >> 3, mxc = m & 7;
            int ty = (q < 2) ? ty0 : ty1;
            int tx = (q < 2) ? tx0 : tx1;
            float v = cc[nt][q] * sc + bs[(ty - my + 7) * 15 + (tx - mxc + 7)];
            if (mhb && ((ty < 4) != (my < 4)))  v -= 100.0f;
            if (mwb && ((tx < 4) != (mxc < 4))) v -= 100.0f;
            cc[nt][q] = v;
        }

    float mx0 = -1e30f, mx1 = -1e30f;
#pragma unroll
    for (int nt = 0; nt < 8; ++nt) {
        mx0 = fmaxf(mx0, fmaxf(cc[nt][0], cc[nt][1]));
        mx1 = fmaxf(mx1, fmaxf(cc[nt][2], cc[nt][3]));
    }
    mx0 = fmaxf(mx0, __shfl_xor_sync(0xffffffffu, mx0, 1));
    mx0 = fmaxf(mx0, __shfl_xor_sync(0xffffffffu, mx0, 2));
    mx1 = fmaxf(mx1, __shfl_xor_sync(0xffffffffu, mx1, 1));
    mx1 = fmaxf(mx1, __shfl_xor_sync(0xffffffffu, mx1, 2));

    float s0 = 0.0f, s1 = 0.0f;
#pragma unroll
    for (int nt = 0; nt < 8; ++nt) {
        cc[nt][0] = __expf(cc[nt][0] - mx0);
        cc[nt][1] = __expf(cc[nt][1] - mx0);
        cc[nt][2] = __expf(cc[nt][2] - mx1);
        cc[nt][3] = __expf(cc[nt][3] - mx1);
        s0 += cc[nt][0] + cc[nt][1];
        s1 += cc[nt][2] + cc[nt][3];
    }
    s0 += __shfl_xor_sync(0xffffffffu, s0, 1);
    s0 += __shfl_xor_sync(0xffffffffu, s0, 2);
    s1 += __shfl_xor_sync(0xffffffffu, s1, 1);
    s1 += __shfl_xor_sync(0xffffffffu, s1, 2);
    const float inv0 = 1.0f / s0;
    const float inv1 = 1.0f / s1;

    unsigned* psw = ps[wt];
#pragma unroll
    for (int nt = 0; nt < 8; ++nt) {
        psw[g * 36 + nt * 4 + t]       = pkh(cc[nt][0], cc[nt][1]);
        psw[(g + 8) * 36 + nt * 4 + t] = pkh(cc[nt][2], cc[nt][3]);
    }
    __syncwarp();

    const unsigned ps_b  = (unsigned)__cvta_generic_to_shared(ps[wt]);
    const unsigned vts_b = (unsigned)__cvta_generic_to_shared(vts);
    float out[4][4];
#pragma unroll
    for (int vt = 0; vt < 4; ++vt)
#pragma unroll
        for (int q = 0; q < 4; ++q) out[vt][q] = 0.0f;

#pragma unroll
    for (int kb = 0; kb < 4; ++kb) {
        unsigned a4[4];
        ldsm4(a4, ps_b + alm * 144 + kb * 32 + alk);
#pragma unroll
        for (int vtp = 0; vtp < 2; ++vtp) {
            unsigned b4[4];
            ldsm4(b4, vts_b + (vtp * 16 + blm) * 144 + kb * 32 + blk);
            mma16(out[2 * vtp],     a4, b4);
            mma16(out[2 * vtp + 1], a4, b4 + 2);
        }
    }

    const int d0i = (((w << 6) | r0) << 8) + h * 32;
    const int d1i = (((w << 6) | r1) << 8) + h * 32;
    unsigned* ao32 = (unsigned*)g_ao;
#pragma unroll
    for (int vt = 0; vt < 4; ++vt) {
        ao32[(d0i + vt * 8 + 2 * t) >> 1] = pkh(out[vt][0] * inv0, out[vt][1] * inv0);
        ao32[(d1i + vt * 8 + 2 * t) >> 1] = pkh(out[vt][2] * inv1, out[vt][3] * inv1);
    }
}

// ============================================================
// Kernel 3: output projection, halved N tile, 3-stage, 2 CTAs/SM.
// grid 1024: x = bw*2+nh.
// ============================================================
__global__ void __launch_bounds__(512, 2)
swin_proj_kernel(const float* __restrict__ bo, float* __restrict__ out)
{
    extern __shared__ char smem[];
    const unsigned sb = (unsigned)__cvta_generic_to_shared(smem);
    float* bias_s = (float*)(smem + H_BIAS);

    const int bx   = blockIdx.x;
    const int bw   = bx >> 1;
    const int nh   = bx & 1;
    const int tid  = threadIdx.x;
    const int warp = tid >> 5;
    const int lane = tid & 31;
    const int g    = lane >> 2;
    const int t    = lane & 3;
    const int mw   = warp >> 2;
    const int nq   = warp & 3;

    const unsigned alm = lane & 15;
    const unsigned alk = (lane >> 4) << 4;
    const unsigned blm = (lane & 7) + ((lane >> 4) << 3);
    const unsigned blk = ((lane >> 3) & 1) << 4;

    if (tid < 128) bias_s[tid] = bo[nh * 128 + tid];
    __syncthreads();

    const int srow = tid >> 3;
    const int sjj  = tid & 7;
    const unsigned sto0 = srow * 144 + sjj * 16;
    const unsigned sto1 = (srow + 64) * 144 + sjj * 16;
    const unsigned short* wh = g_wh + 3 * 65536 + (nh << 15);
    const int abase = bw * 128 * 256;

#define STAGE(c_, st_) do {                                                    \
        unsigned _a = sb + H_BUF + (st_) * HSTG;                               \
        cp16(_a + sto0, g_ao + abase + srow * 256 + (c_) * 64 + sjj * 8);      \
        cp16(_a + sto1, g_ao + abase + (srow + 64) * 256 + (c_) * 64 + sjj * 8); \
        unsigned _bB = _a + HA_BYTES;                                          \
        cp16(_bB + sto0, wh + srow * 256 + (c_) * 64 + sjj * 8);               \
        cp16(_bB + sto1, wh + (srow + 64) * 256 + (c_) * 64 + sjj * 8);        \
        cp_commit();                                                           \
    } while (0)

    STAGE(0, 0); STAGE(1, 1); STAGE(2, 2);

    float acc[2][4][4];
#pragma unroll
    for (int mt = 0; mt < 2; ++mt)
#pragma unroll
        for (int nt = 0; nt < 4; ++nt)
#pragma unroll
            for (int q = 0; q < 4; ++q) acc[mt][nt][q] = 0.0f;

#pragma unroll 1
    for (int c = 0; c < 4; ++c) {
        if      (c == 0) cp_wait<2>();
        else if (c == 1) cp_wait<1>();
        else if (c == 2) cp_wait<1>();
        else             cp_wait<0>();
        __syncthreads();
        if (c == 1) STAGE(3, 0);

        const unsigned sbX = sb + H_BUF + (c % 3) * HSTG;
        const unsigned sbB = sbX + HA_BYTES;
#pragma unroll
        for (int ks = 0; ks < 4; ++ks) {
            unsigned a[2][4];
            ldsm4(a[0], sbX + (mw * 32 + alm) * 144 + ks * 32 + alk);
            ldsm4(a[1], sbX + (mw * 32 + 16 + alm) * 144 + ks * 32 + alk);
#pragma unroll
            for (int ntp = 0; ntp < 2; ++ntp) {
                unsigned b4[4];
                ldsm4(b4, sbB + (nq * 32 + ntp * 16 + blm) * 144 + ks * 32 + blk);
                mma16(acc[0][2 * ntp],     a[0], b4);
                mma16(acc[0][2 * ntp + 1], a[0], b4 + 2);
                mma16(acc[1][2 * ntp],     a[1], b4);
                mma16(acc[1][2 * ntp + 1], a[1], b4 + 2);
            }
        }
    }
#undef STAGE

    float2 bb[4];
#pragma unroll
    for (int nt = 0; nt < 4; ++nt)
        bb[nt] = *(float2*)(bias_s + nq * 32 + nt * 8 + 2 * t);

#pragma unroll
    for (int mt = 0; mt < 2; ++mt)
#pragma unroll
        for (int rh = 0; rh < 2; ++rh)
#pragma unroll
            for (int nt = 0; nt < 4; ++nt) {
                int n   = mw * 32 + mt * 16 + rh * 8 + g;
                int wv  = bw * 2 + (n >> 6);
                int tok = n & 63;
                int b   = wv >> 6, wy = (wv >> 3) & 7, wx = wv & 7;
                int y   = ((wy << 3) + (tok >> 3) + 4) & 63;
                int xc  = ((wx << 3) + (tok & 7) + 4) & 63;
                int col = nh * 128 + nq * 32 + nt * 8 + 2 * t;
                *(float2*)(out + (((b << 6) | y) << 14) + (xc << 8) + col) =
                    make_float2(acc[mt][nt][rh * 2] + bb[nt].x,
                                acc[mt][nt][rh * 2 + 1] + bb[nt].y);
            }
}

// ============================================================
extern "C" void kernel_launch(void* const* d_in, const int* in_sizes, int n_in,
                              void* d_out, int out_size)
{
    const float* x  = (const float*)d_in[0];
    const float* Wq = (const float*)d_in[1];
    const float* bq = (const float*)d_in[2];
    const float* Wk = (const float*)d_in[3];
    const float* bk = (const float*)d_in[4];
    const float* Wv = (const float*)d_in[5];
    const float* bv = (const float*)d_in[6];
    const float* Wo = (const float*)d_in[7];
    const float* bo = (const float*)d_in[8];
    const float* ls = (const float*)d_in[9];
    const float* w1 = (const float*)d_in[10];
    const float* b1 = (const float*)d_in[11];
    const float* w2 = (const float*)d_in[12];
    float* out = (float*)d_out;

    cudaFuncSetAttribute(swin_qkv_kernel,
                         cudaFuncAttributeMaxDynamicSharedMemorySize, H_SMEM);
    cudaFuncSetAttribute(swin_proj_kernel,
                         cudaFuncAttributeMaxDynamicSharedMemorySize, H_SMEM);

    swin_bias_kernel<<<225, 512>>>(ls, w1, b1, w2);
    swin_cvt_kernel<<<16640, 256>>>(x, Wq, Wk, Wv, Wo);
    swin_qkv_kernel<<<dim3(1024, 3), 512, H_SMEM>>>(bq, bk, bv);
    swin_attn_kernel<<<dim3(NWIN, NHEAD), 128>>>();
    swin_proj_kernel<<<1024, 512, H_SMEM>>>(bo, out);
}